// round 10
// baseline (speedup 1.0000x reference)
#include <cuda_runtime.h>
#include <cuda_fp16.h>
#include <cuda_bf16.h>

#define N_NODES 600000
#define N_EDGES 2400000
#define LEADS 12
#define NUM_GRAPHS 50000
#define F_IN 128
#define HDIM 64
#define OUT_DIM 32

#define SCAN_NB 586   // ceil(600000/1024)

// ---------------- packed fp32x2 FMA (used in attention) ------------------------
__device__ __forceinline__ void fma2(unsigned long long& d,
                                     unsigned long long a,
                                     unsigned long long b) {
    asm("fma.rn.f32x2 %0, %1, %2, %0;" : "+l"(d) : "l"(a), "l"(b));
}
__device__ __forceinline__ float hsum2(unsigned long long d) {
    float lo = __uint_as_float((unsigned int)(d & 0xffffffffULL));
    float hi = __uint_as_float((unsigned int)(d >> 32));
    return lo + hi;
}

// ---------------- bf16 mma m16n8k16, fp32 accumulate ---------------------------
__device__ __forceinline__ void mma_bf16(float* c, const unsigned* a,
                                         unsigned b0, unsigned b1) {
    asm volatile(
        "mma.sync.aligned.m16n8k16.row.col.f32.bf16.bf16.f32 "
        "{%0,%1,%2,%3}, {%4,%5,%6,%7}, {%8,%9}, {%0,%1,%2,%3};"
        : "+f"(c[0]), "+f"(c[1]), "+f"(c[2]), "+f"(c[3])
        : "r"(a[0]), "r"(a[1]), "r"(a[2]), "r"(a[3]), "r"(b0), "r"(b1));
}

// ---------------- scratch (device globals) ------------------------------------
__device__ __half g_hH  [(size_t)N_NODES * HDIM];  // GEMM output (gather source)
__device__ __half g_aggH[(size_t)N_NODES * HDIM];  // aggregated layer output
__device__ float  g_dinv[N_NODES];
__device__ int    g_deg[N_NODES];
__device__ int    g_rowoff[N_NODES + 1];
__device__ int    g_cursor[N_NODES];
__device__ int    g_csr[N_EDGES];
__device__ int    g_bsum[SCAN_NB];
__device__ int    g_boff[SCAN_NB];

// ---------------- degree / CSR build -------------------------------------------
__global__ void k_deg_zero() {
    int i = blockIdx.x * blockDim.x + threadIdx.x;
    if (i < N_NODES) g_deg[i] = 0;
}

__global__ void k_deg_count(const int* __restrict__ dst) {
    int e = blockIdx.x * blockDim.x + threadIdx.x;
    if (e < N_EDGES) atomicAdd(&g_deg[dst[e]], 1);
}

__global__ void k_dinv() {
    int i = blockIdx.x * blockDim.x + threadIdx.x;
    if (i < N_NODES) g_dinv[i] = rsqrtf((float)(g_deg[i] + 1));
}

__global__ void k_scan1() {
    __shared__ int sh[1024];
    int i = blockIdx.x * 1024 + threadIdx.x;
    int v = (i < N_NODES) ? g_deg[i] : 0;
    sh[threadIdx.x] = v;
    __syncthreads();
    #pragma unroll
    for (int off = 1; off < 1024; off <<= 1) {
        int t = 0;
        if (threadIdx.x >= off) t = sh[threadIdx.x - off];
        __syncthreads();
        if (threadIdx.x >= off) sh[threadIdx.x] += t;
        __syncthreads();
    }
    if (i < N_NODES) g_rowoff[i] = sh[threadIdx.x] - v;   // exclusive
    if (threadIdx.x == 1023) g_bsum[blockIdx.x] = sh[1023];
}

__global__ void k_scan2() {
    __shared__ int sh[1024];
    int v = (threadIdx.x < SCAN_NB) ? g_bsum[threadIdx.x] : 0;
    sh[threadIdx.x] = v;
    __syncthreads();
    #pragma unroll
    for (int off = 1; off < 1024; off <<= 1) {
        int t = 0;
        if (threadIdx.x >= off) t = sh[threadIdx.x - off];
        __syncthreads();
        if (threadIdx.x >= off) sh[threadIdx.x] += t;
        __syncthreads();
    }
    if (threadIdx.x < SCAN_NB) g_boff[threadIdx.x] = sh[threadIdx.x] - v;
}

__global__ void k_scan3() {
    int i = blockIdx.x * blockDim.x + threadIdx.x;
    if (i < N_NODES) {
        int ro = g_rowoff[i] + g_boff[i >> 10];
        g_rowoff[i] = ro;
        g_cursor[i] = ro;
    }
    if (i == 0) g_rowoff[N_NODES] = N_EDGES;
}

__global__ void k_place(const int* __restrict__ src, const int* __restrict__ dst) {
    int e = blockIdx.x * blockDim.x + threadIdx.x;
    if (e < N_EDGES) {
        int pos = atomicAdd(&g_cursor[dst[e]], 1);
        g_csr[pos] = src[e];
    }
}

// ---------------- tensor-core GEMM: C_fp16 = (act(A) @ W) * dinv[row] ----------
// bf16 split (hi+lo), 3 HMMA products, fp32 accumulate. 256 threads, BM=128.
// All staging loads batched up front (max MLP).
template<int K, bool ACT, bool HALF_IN>
__global__ void k_gemm_mma(const void* __restrict__ Ain, const float* __restrict__ W,
                           const float* __restrict__ bias, __half* __restrict__ C) {
    constexpr int BM = 128;
    constexpr int KP = K + 8;    // padded row
    constexpr int KQ = K / 4;
    constexpr int NIT = BM * KQ / 256;   // staging vectors per thread (16 / 8)
    extern __shared__ char smem_raw[];
    __nv_bfloat16* sAhi = (__nv_bfloat16*)smem_raw;            // [BM][KP]
    __nv_bfloat16* sAlo = sAhi + BM * KP;                      // [BM][KP]
    __nv_bfloat16* sWhi = sAlo + BM * KP;                      // [64][KP] (transposed)
    __nv_bfloat16* sWlo = sWhi + 64 * KP;                      // [64][KP]

    const int tid = threadIdx.x;
    const int r0 = blockIdx.x * BM;

    // stage A split hi/lo (+ optional fused bias+relu); ALL loads issued first
    const float4* B4 = (const float4*)bias;
    {
        float av[NIT][4];
        #pragma unroll
        for (int j = 0; j < NIT; j++) {
            int i = tid + j * 256;
            int row = i / KQ, kq = i - row * KQ;
            av[j][0] = 0.f; av[j][1] = 0.f; av[j][2] = 0.f; av[j][3] = 0.f;
            if (r0 + row < N_NODES) {
                if (HALF_IN) {
                    uint2 u = __ldg(((const uint2*)Ain) + (size_t)(r0 + row) * KQ + kq);
                    float2 f0 = __half22float2(*(const __half2*)&u.x);
                    float2 f1 = __half22float2(*(const __half2*)&u.y);
                    av[j][0] = f0.x; av[j][1] = f0.y; av[j][2] = f1.x; av[j][3] = f1.y;
                } else {
                    float4 a = __ldg(((const float4*)Ain) + (size_t)(r0 + row) * KQ + kq);
                    av[j][0] = a.x; av[j][1] = a.y; av[j][2] = a.z; av[j][3] = a.w;
                }
            }
        }
        // W staging overlaps with A-load latency
        for (int i = tid; i < K * 64; i += 256) {
            int k = i >> 6, c = i & 63;
            float w = W[i];
            __nv_bfloat16 hi = __float2bfloat16_rn(w);
            sWhi[c * KP + k] = hi;
            sWlo[c * KP + k] = __float2bfloat16_rn(w - __bfloat162float(hi));
        }
        #pragma unroll
        for (int j = 0; j < NIT; j++) {
            int i = tid + j * 256;
            int row = i / KQ, kq = i - row * KQ;
            if (ACT) {
                float4 b = B4[kq];
                av[j][0] = fmaxf(av[j][0] + b.x, 0.f);
                av[j][1] = fmaxf(av[j][1] + b.y, 0.f);
                av[j][2] = fmaxf(av[j][2] + b.z, 0.f);
                av[j][3] = fmaxf(av[j][3] + b.w, 0.f);
            }
            __nv_bfloat16 hv[4], lv[4];
            #pragma unroll
            for (int q = 0; q < 4; q++) {
                hv[q] = __float2bfloat16_rn(av[j][q]);
                lv[q] = __float2bfloat16_rn(av[j][q] - __bfloat162float(hv[q]));
            }
            __nv_bfloat162* ph = (__nv_bfloat162*)(sAhi + row * KP + kq * 4);
            __nv_bfloat162* pl = (__nv_bfloat162*)(sAlo + row * KP + kq * 4);
            ph[0] = __nv_bfloat162(hv[0], hv[1]);
            ph[1] = __nv_bfloat162(hv[2], hv[3]);
            pl[0] = __nv_bfloat162(lv[0], lv[1]);
            pl[1] = __nv_bfloat162(lv[2], lv[3]);
        }
    }
    __syncthreads();

    const int warp = tid >> 5;
    const int lane = tid & 31;
    const int g  = lane >> 2;       // fragment group row / B col
    const int t2 = (lane & 3) * 2;  // fragment k-pair base
    const int wrow = warp * 16;     // warp's first row in block

    float acc[8][4];
    #pragma unroll
    for (int n = 0; n < 8; n++)
        #pragma unroll
        for (int c = 0; c < 4; c++) acc[n][c] = 0.f;

    #pragma unroll
    for (int kb = 0; kb < K / 16; kb++) {
        const int kO = kb * 16 + t2;
        unsigned ahi[4], alo[4];
        {
            int rA = wrow + g;
            const unsigned* pH0 = (const unsigned*)(sAhi + rA * KP + kO);
            const unsigned* pH8 = (const unsigned*)(sAhi + (rA + 8) * KP + kO);
            const unsigned* pL0 = (const unsigned*)(sAlo + rA * KP + kO);
            const unsigned* pL8 = (const unsigned*)(sAlo + (rA + 8) * KP + kO);
            ahi[0] = pH0[0]; ahi[1] = pH8[0]; ahi[2] = pH0[4]; ahi[3] = pH8[4];
            alo[0] = pL0[0]; alo[1] = pL8[0]; alo[2] = pL0[4]; alo[3] = pL8[4];
        }
        #pragma unroll
        for (int n = 0; n < 8; n++) {
            int rB = n * 8 + g;
            const unsigned* qH = (const unsigned*)(sWhi + rB * KP + kO);
            const unsigned* qL = (const unsigned*)(sWlo + rB * KP + kO);
            unsigned bh0 = qH[0], bh1 = qH[4];
            unsigned bl0 = qL[0], bl1 = qL[4];
            mma_bf16(acc[n], ahi, bh0, bh1);
            mma_bf16(acc[n], ahi, bl0, bl1);
            mma_bf16(acc[n], alo, bh0, bh1);
        }
    }

    // epilogue: scale by dinv[row], write fp16
    __half2* C2 = (__half2*)C;
    int r  = r0 + wrow + g;
    int r8 = r + 8;
    float dv  = (r  < N_NODES) ? g_dinv[r]  : 0.f;
    float dv8 = (r8 < N_NODES) ? g_dinv[r8] : 0.f;
    #pragma unroll
    for (int n = 0; n < 8; n++) {
        if (r < N_NODES)
            C2[(size_t)r * 32 + n * 4 + (t2 >> 1)] =
                __floats2half2_rn(acc[n][0] * dv, acc[n][1] * dv);
        if (r8 < N_NODES)
            C2[(size_t)r8 * 32 + n * 4 + (t2 >> 1)] =
                __floats2half2_rn(acc[n][2] * dv8, acc[n][3] * dv8);
    }
}

// ---------------- CSR aggregation: warp/node, shfl-batched indices -------------
// CSR segment loaded lane-parallel (1 coalesced LDG per 32 edges), indices
// broadcast via shfl, gathers issued 4-wide with independent accumulators.
__global__ void k_aggregate() {
    int node = (blockIdx.x * blockDim.x + threadIdx.x) >> 5;
    if (node >= N_NODES) return;
    const int lane = threadIdx.x & 31;
    const __half2* h2 = (const __half2*)g_hH;   // row = 32 half2

    float2 a0 = __half22float2(h2[(size_t)node * 32 + lane]);   // self
    float2 a1 = make_float2(0.f, 0.f);
    float2 a2 = make_float2(0.f, 0.f);
    float2 a3 = make_float2(0.f, 0.f);

    int e0 = g_rowoff[node];
    int deg = g_rowoff[node + 1] - e0;

    for (int base = 0; base < deg; base += 32) {
        int rem = deg - base;
        int cnt = rem < 32 ? rem : 32;
        int s = (lane < cnt) ? __ldg(&g_csr[e0 + base + lane]) : 0;
        int j = 0;
        for (; j + 4 <= cnt; j += 4) {
            int s0 = __shfl_sync(0xffffffff, s, j);
            int s1 = __shfl_sync(0xffffffff, s, j + 1);
            int s2 = __shfl_sync(0xffffffff, s, j + 2);
            int s3 = __shfl_sync(0xffffffff, s, j + 3);
            float2 v0 = __half22float2(h2[(size_t)s0 * 32 + lane]);
            float2 v1 = __half22float2(h2[(size_t)s1 * 32 + lane]);
            float2 v2 = __half22float2(h2[(size_t)s2 * 32 + lane]);
            float2 v3 = __half22float2(h2[(size_t)s3 * 32 + lane]);
            a0.x += v0.x; a0.y += v0.y;
            a1.x += v1.x; a1.y += v1.y;
            a2.x += v2.x; a2.y += v2.y;
            a3.x += v3.x; a3.y += v3.y;
        }
        for (; j < cnt; j++) {
            int s0 = __shfl_sync(0xffffffff, s, j);
            float2 v0 = __half22float2(h2[(size_t)s0 * 32 + lane]);
            a0.x += v0.x; a0.y += v0.y;
        }
    }

    float dv = g_dinv[node];
    ((__half2*)g_aggH)[(size_t)node * 32 + lane] =
        __floats2half2_rn((a0.x + a1.x + a2.x + a3.x) * dv,
                          (a0.y + a1.y + a2.y + a3.y) * dv);
}

// ---------------- attention + pooling + final linear ---------------------------
__global__ void k_attn(const float* __restrict__ Wa, const float* __restrict__ v,
                       const float* __restrict__ Wl, const float* __restrict__ bl,
                       const float* __restrict__ b3,
                       float* __restrict__ out, float* __restrict__ lw) {
    __shared__ float sWaT[64 * 68];
    __shared__ float sWl[128 * 32];
    __shared__ float sV[64];
    __shared__ float sBl[32];
    __shared__ float sB3[64];
    __shared__ float sH[8][LEADS * 64];
    __shared__ float sScore[8][LEADS];
    __shared__ float sPool[8][128];

    int tid = threadIdx.x;
    for (int i = tid; i < 4096; i += 256) {
        int k = i >> 6, c = i & 63;
        sWaT[c * 68 + k] = Wa[i];
        sWl[i] = Wl[i];
    }
    if (tid < 64) { sV[tid] = v[tid]; sB3[tid] = b3[tid]; }
    if (tid < 32) sBl[tid] = bl[tid];
    __syncthreads();

    int w = tid >> 5, lane = tid & 31;
    int g = blockIdx.x * 8 + w;
    if (g >= NUM_GRAPHS) return;

    float* hs = sH[w];
    const uint4* hg = (const uint4*)(g_aggH + (size_t)g * (LEADS * 64));  // 96 uint4
    #pragma unroll
    for (int j = 0; j < 3; j++) {
        int id = lane + 32 * j;      // 0..95
        uint4 u = hg[id];
        int lead = id >> 3;
        int fb = (id & 7) * 8;
        const __half2* p = (const __half2*)&u;
        #pragma unroll
        for (int i = 0; i < 4; i++) {
            float2 f = __half22float2(p[i]);
            hs[lead * 64 + fb + 2 * i]     = fmaxf(f.x + sB3[fb + 2 * i], 0.f);
            hs[lead * 64 + fb + 2 * i + 1] = fmaxf(f.y + sB3[fb + 2 * i + 1], 0.f);
        }
    }
    __syncwarp();

    unsigned long long e0a[LEADS], e1a[LEADS];
    #pragma unroll
    for (int l = 0; l < LEADS; l++) { e0a[l] = 0ULL; e1a[l] = 0ULL; }
    const float* w0base = sWaT + lane * 68;
    const float* w1base = sWaT + (lane + 32) * 68;
    #pragma unroll 4
    for (int k4 = 0; k4 < 16; k4++) {
        ulonglong2 w0 = *(const ulonglong2*)(w0base + k4 * 4);
        ulonglong2 w1 = *(const ulonglong2*)(w1base + k4 * 4);
        #pragma unroll
        for (int l = 0; l < LEADS; l++) {
            ulonglong2 a = *(const ulonglong2*)(hs + l * 64 + k4 * 4);
            fma2(e0a[l], a.x, w0.x); fma2(e0a[l], a.y, w0.y);
            fma2(e1a[l], a.x, w1.x); fma2(e1a[l], a.y, w1.y);
        }
    }
    float v0 = sV[lane], v1 = sV[lane + 32];
    #pragma unroll
    for (int l = 0; l < LEADS; l++) {
        float s = tanhf(hsum2(e0a[l])) * v0 + tanhf(hsum2(e1a[l])) * v1;
        #pragma unroll
        for (int o = 16; o > 0; o >>= 1) s += __shfl_xor_sync(0xffffffff, s, o);
        if (lane == 0) sScore[w][l] = s;
    }
    __syncwarp();

    float sc[LEADS];
    #pragma unroll
    for (int l = 0; l < LEADS; l++) sc[l] = sScore[w][l];
    float m = sc[0];
    #pragma unroll
    for (int l = 1; l < LEADS; l++) m = fmaxf(m, sc[l]);
    float sum = 0.f;
    #pragma unroll
    for (int l = 0; l < LEADS; l++) { sc[l] = expf(sc[l] - m); sum += sc[l]; }
    float inv = 1.f / sum;
    #pragma unroll
    for (int l = 0; l < LEADS; l++) sc[l] *= inv;
    if (lane < LEADS) lw[(size_t)g * LEADS + lane] = sc[lane];

    #pragma unroll
    for (int half = 0; half < 2; half++) {
        int f = lane + 32 * half;
        float mx = -1e30f, sm = 0.f;
        #pragma unroll
        for (int l = 0; l < LEADS; l++) {
            float val = hs[l * 64 + f] * sc[l];
            mx = fmaxf(mx, val);
            sm += val;
        }
        sPool[w][f] = mx;
        sPool[w][64 + f] = sm * (1.f / 12.f);
    }
    __syncwarp();

    float acc = sBl[lane];
    #pragma unroll 16
    for (int f = 0; f < 128; f++) acc += sPool[w][f] * sWl[f * 32 + lane];
    out[(size_t)g * 32 + lane] = fmaxf(acc, 0.f);
}

// ---------------- launch --------------------------------------------------------
extern "C" void kernel_launch(void* const* d_in, const int* in_sizes, int n_in,
                              void* d_out, int out_size) {
    const float* x    = (const float*)d_in[0];
    const int*   ei   = (const int*)d_in[1];
    const int*   srcp = ei;
    const int*   dstp = ei + N_EDGES;
    const float* W1 = (const float*)d_in[3];
    const float* b1 = (const float*)d_in[4];
    const float* W2 = (const float*)d_in[5];
    const float* b2 = (const float*)d_in[6];
    const float* W3 = (const float*)d_in[7];
    const float* b3 = (const float*)d_in[8];
    const float* Wa = (const float*)d_in[9];
    const float* vv = (const float*)d_in[10];
    const float* Wl = (const float*)d_in[11];
    const float* bl = (const float*)d_in[12];

    float* out = (float*)d_out;                                  // [G,32]
    float* lw  = (float*)d_out + (size_t)NUM_GRAPHS * OUT_DIM;   // [G,12]

    __half* hp;  cudaGetSymbolAddress((void**)&hp,  g_hH);
    __half* ap;  cudaGetSymbolAddress((void**)&ap,  g_aggH);

    const int SM1 = (2 * 128 + 2 * 64) * (128 + 8) * 2;   // 104448 B
    const int SM2 = (2 * 128 + 2 * 64) * (64 + 8) * 2;    //  55296 B
    cudaFuncSetAttribute(k_gemm_mma<128, false, false>, cudaFuncAttributeMaxDynamicSharedMemorySize, SM1);
    cudaFuncSetAttribute(k_gemm_mma<64, true, true>,   cudaFuncAttributeMaxDynamicSharedMemorySize, SM2);

    const int T = 256;
    const int gN = (N_NODES + T - 1) / T;
    const int gE = (N_EDGES + T - 1) / T;
    const int GRID = (N_NODES + 127) / 128;
    const int AGG_GRID = (int)(((size_t)N_NODES * 32 + T - 1) / T);

    // launches 1-3
    k_deg_zero<<<gN, T>>>();
    k_deg_count<<<gE, T>>>(dstp);
    k_dinv<<<gN, T>>>();

    // launch 4 (ncu-profiled slot): tensor-core layer-1 GEMM
    k_gemm_mma<128, false, false><<<GRID, 256, SM1>>>(x, W1, nullptr, hp);

    // CSR build
    k_scan1<<<SCAN_NB, 1024>>>();
    k_scan2<<<1, 1024>>>();
    k_scan3<<<(N_NODES + 1023) / 1024, 1024>>>();
    k_place<<<gE, T>>>(srcp, dstp);

    k_aggregate<<<AGG_GRID, T>>>();
    k_gemm_mma<64, true, true><<<GRID, 256, SM2>>>(ap, W2, b1, hp);
    k_aggregate<<<AGG_GRID, T>>>();
    k_gemm_mma<64, true, true><<<GRID, 256, SM2>>>(ap, W3, b2, hp);
    k_aggregate<<<AGG_GRID, T>>>();

    k_attn<<<(NUM_GRAPHS + 7) / 8, 256>>>(Wa, vv, Wl, bl, b3, out, lw);
}

// round 11
// speedup vs baseline: 1.2646x; 1.2646x over previous
#include <cuda_runtime.h>
#include <cuda_fp16.h>
#include <cuda_bf16.h>

#define N_NODES 600000
#define N_EDGES 2400000
#define LEADS 12
#define NUM_GRAPHS 50000
#define F_IN 128
#define HDIM 64
#define OUT_DIM 32

#define SCAN_NB 586   // ceil(600000/1024)

// ---------------- packed fp32x2 FMA (used in attention) ------------------------
__device__ __forceinline__ void fma2(unsigned long long& d,
                                     unsigned long long a,
                                     unsigned long long b) {
    asm("fma.rn.f32x2 %0, %1, %2, %0;" : "+l"(d) : "l"(a), "l"(b));
}
__device__ __forceinline__ float hsum2(unsigned long long d) {
    float lo = __uint_as_float((unsigned int)(d & 0xffffffffULL));
    float hi = __uint_as_float((unsigned int)(d >> 32));
    return lo + hi;
}

// ---------------- bf16 mma m16n8k16, fp32 accumulate ---------------------------
__device__ __forceinline__ void mma_bf16(float* c, const unsigned* a,
                                         unsigned b0, unsigned b1) {
    asm volatile(
        "mma.sync.aligned.m16n8k16.row.col.f32.bf16.bf16.f32 "
        "{%0,%1,%2,%3}, {%4,%5,%6,%7}, {%8,%9}, {%0,%1,%2,%3};"
        : "+f"(c[0]), "+f"(c[1]), "+f"(c[2]), "+f"(c[3])
        : "r"(a[0]), "r"(a[1]), "r"(a[2]), "r"(a[3]), "r"(b0), "r"(b1));
}

// ---------------- scratch (device globals) ------------------------------------
__device__ __half g_hH  [(size_t)N_NODES * HDIM];  // GEMM output (gather source)
__device__ __half g_aggH[(size_t)N_NODES * HDIM];  // aggregated layer output
__device__ float  g_dinv[N_NODES];
__device__ int    g_deg[N_NODES];
__device__ int    g_rowoff[N_NODES + 1];
__device__ int    g_cursor[N_NODES];
__device__ int    g_csr[N_EDGES];
__device__ int    g_bsum[SCAN_NB];
__device__ int    g_boff[SCAN_NB];

// ---------------- degree / CSR build -------------------------------------------
__global__ void k_deg_zero() {
    int i = blockIdx.x * blockDim.x + threadIdx.x;
    if (i < N_NODES) g_deg[i] = 0;
}

__global__ void k_deg_count(const int* __restrict__ dst) {
    int e = blockIdx.x * blockDim.x + threadIdx.x;
    if (e < N_EDGES) atomicAdd(&g_deg[dst[e]], 1);
}

__global__ void k_dinv() {
    int i = blockIdx.x * blockDim.x + threadIdx.x;
    if (i < N_NODES) g_dinv[i] = rsqrtf((float)(g_deg[i] + 1));
}

__global__ void k_scan1() {
    __shared__ int sh[1024];
    int i = blockIdx.x * 1024 + threadIdx.x;
    int v = (i < N_NODES) ? g_deg[i] : 0;
    sh[threadIdx.x] = v;
    __syncthreads();
    #pragma unroll
    for (int off = 1; off < 1024; off <<= 1) {
        int t = 0;
        if (threadIdx.x >= off) t = sh[threadIdx.x - off];
        __syncthreads();
        if (threadIdx.x >= off) sh[threadIdx.x] += t;
        __syncthreads();
    }
    if (i < N_NODES) g_rowoff[i] = sh[threadIdx.x] - v;   // exclusive
    if (threadIdx.x == 1023) g_bsum[blockIdx.x] = sh[1023];
}

__global__ void k_scan2() {
    __shared__ int sh[1024];
    int v = (threadIdx.x < SCAN_NB) ? g_bsum[threadIdx.x] : 0;
    sh[threadIdx.x] = v;
    __syncthreads();
    #pragma unroll
    for (int off = 1; off < 1024; off <<= 1) {
        int t = 0;
        if (threadIdx.x >= off) t = sh[threadIdx.x - off];
        __syncthreads();
        if (threadIdx.x >= off) sh[threadIdx.x] += t;
        __syncthreads();
    }
    if (threadIdx.x < SCAN_NB) g_boff[threadIdx.x] = sh[threadIdx.x] - v;
}

__global__ void k_scan3() {
    int i = blockIdx.x * blockDim.x + threadIdx.x;
    if (i < N_NODES) {
        int ro = g_rowoff[i] + g_boff[i >> 10];
        g_rowoff[i] = ro;
        g_cursor[i] = ro;
    }
    if (i == 0) g_rowoff[N_NODES] = N_EDGES;
}

__global__ void k_place(const int* __restrict__ src, const int* __restrict__ dst) {
    int e = blockIdx.x * blockDim.x + threadIdx.x;
    if (e < N_EDGES) {
        int pos = atomicAdd(&g_cursor[dst[e]], 1);
        g_csr[pos] = src[e];
    }
}

// ---------------- tensor-core GEMM: C_fp16 = (act(A) @ W) * dinv[row] ----------
// bf16 split (hi+lo), 3 HMMA products, fp32 accumulate. 256 threads, BM=128.
// Staging loads front-batched 8-wide (R9-best config).
template<int K, bool ACT, bool HALF_IN>
__global__ void k_gemm_mma(const void* __restrict__ Ain, const float* __restrict__ W,
                           const float* __restrict__ bias, __half* __restrict__ C) {
    constexpr int BM = 128;
    constexpr int KP = K + 8;    // padded row
    constexpr int KQ = K / 4;
    constexpr int NIT = BM * KQ / 256;   // staging iterations (16 for K=128, 8 for K=64)
    extern __shared__ char smem_raw[];
    __nv_bfloat16* sAhi = (__nv_bfloat16*)smem_raw;            // [BM][KP]
    __nv_bfloat16* sAlo = sAhi + BM * KP;                      // [BM][KP]
    __nv_bfloat16* sWhi = sAlo + BM * KP;                      // [64][KP] (transposed)
    __nv_bfloat16* sWlo = sWhi + 64 * KP;                      // [64][KP]

    const int tid = threadIdx.x;
    const int r0 = blockIdx.x * BM;

    // stage W transposed, split hi/lo
    for (int i = tid; i < K * 64; i += 256) {
        int k = i >> 6, c = i & 63;
        float w = W[i];
        __nv_bfloat16 hi = __float2bfloat16_rn(w);
        sWhi[c * KP + k] = hi;
        sWlo[c * KP + k] = __float2bfloat16_rn(w - __bfloat162float(hi));
    }

    // stage A split hi/lo (+ optional fused bias+relu), front-batched loads
    const float4* B4 = (const float4*)bias;
    #pragma unroll
    for (int base = 0; base < NIT; base += 8) {
        float av[8][4];
        #pragma unroll
        for (int j = 0; j < 8; j++) {
            int i = tid + (base + j) * 256;
            int row = i / KQ, kq = i - row * KQ;
            av[j][0] = 0.f; av[j][1] = 0.f; av[j][2] = 0.f; av[j][3] = 0.f;
            if (r0 + row < N_NODES) {
                if (HALF_IN) {
                    uint2 u = __ldg(((const uint2*)Ain) + (size_t)(r0 + row) * KQ + kq);
                    float2 f0 = __half22float2(*(const __half2*)&u.x);
                    float2 f1 = __half22float2(*(const __half2*)&u.y);
                    av[j][0] = f0.x; av[j][1] = f0.y; av[j][2] = f1.x; av[j][3] = f1.y;
                } else {
                    float4 a = __ldg(((const float4*)Ain) + (size_t)(r0 + row) * KQ + kq);
                    av[j][0] = a.x; av[j][1] = a.y; av[j][2] = a.z; av[j][3] = a.w;
                }
            }
        }
        #pragma unroll
        for (int j = 0; j < 8; j++) {
            int i = tid + (base + j) * 256;
            int row = i / KQ, kq = i - row * KQ;
            if (ACT) {
                float4 b = B4[kq];
                av[j][0] = fmaxf(av[j][0] + b.x, 0.f);
                av[j][1] = fmaxf(av[j][1] + b.y, 0.f);
                av[j][2] = fmaxf(av[j][2] + b.z, 0.f);
                av[j][3] = fmaxf(av[j][3] + b.w, 0.f);
            }
            __nv_bfloat16 hv[4], lv[4];
            #pragma unroll
            for (int q = 0; q < 4; q++) {
                hv[q] = __float2bfloat16_rn(av[j][q]);
                lv[q] = __float2bfloat16_rn(av[j][q] - __bfloat162float(hv[q]));
            }
            __nv_bfloat162* ph = (__nv_bfloat162*)(sAhi + row * KP + kq * 4);
            __nv_bfloat162* pl = (__nv_bfloat162*)(sAlo + row * KP + kq * 4);
            ph[0] = __nv_bfloat162(hv[0], hv[1]);
            ph[1] = __nv_bfloat162(hv[2], hv[3]);
            pl[0] = __nv_bfloat162(lv[0], lv[1]);
            pl[1] = __nv_bfloat162(lv[2], lv[3]);
        }
    }
    __syncthreads();

    const int warp = tid >> 5;
    const int lane = tid & 31;
    const int g  = lane >> 2;       // fragment group row / B col
    const int t2 = (lane & 3) * 2;  // fragment k-pair base
    const int wrow = warp * 16;     // warp's first row in block

    float acc[8][4];
    #pragma unroll
    for (int n = 0; n < 8; n++)
        #pragma unroll
        for (int c = 0; c < 4; c++) acc[n][c] = 0.f;

    #pragma unroll
    for (int kb = 0; kb < K / 16; kb++) {
        const int kO = kb * 16 + t2;
        unsigned ahi[4], alo[4];
        {
            int rA = wrow + g;
            const unsigned* pH0 = (const unsigned*)(sAhi + rA * KP + kO);
            const unsigned* pH8 = (const unsigned*)(sAhi + (rA + 8) * KP + kO);
            const unsigned* pL0 = (const unsigned*)(sAlo + rA * KP + kO);
            const unsigned* pL8 = (const unsigned*)(sAlo + (rA + 8) * KP + kO);
            ahi[0] = pH0[0]; ahi[1] = pH8[0]; ahi[2] = pH0[4]; ahi[3] = pH8[4];
            alo[0] = pL0[0]; alo[1] = pL8[0]; alo[2] = pL0[4]; alo[3] = pL8[4];
        }
        #pragma unroll
        for (int n = 0; n < 8; n++) {
            int rB = n * 8 + g;
            const unsigned* qH = (const unsigned*)(sWhi + rB * KP + kO);
            const unsigned* qL = (const unsigned*)(sWlo + rB * KP + kO);
            unsigned bh0 = qH[0], bh1 = qH[4];
            unsigned bl0 = qL[0], bl1 = qL[4];
            mma_bf16(acc[n], ahi, bh0, bh1);
            mma_bf16(acc[n], ahi, bl0, bl1);
            mma_bf16(acc[n], alo, bh0, bh1);
        }
    }

    // epilogue: scale by dinv[row], write fp16
    __half2* C2 = (__half2*)C;
    int r  = r0 + wrow + g;
    int r8 = r + 8;
    float dv  = (r  < N_NODES) ? g_dinv[r]  : 0.f;
    float dv8 = (r8 < N_NODES) ? g_dinv[r8] : 0.f;
    #pragma unroll
    for (int n = 0; n < 8; n++) {
        if (r < N_NODES)
            C2[(size_t)r * 32 + n * 4 + (t2 >> 1)] =
                __floats2half2_rn(acc[n][0] * dv, acc[n][1] * dv);
        if (r8 < N_NODES)
            C2[(size_t)r8 * 32 + n * 4 + (t2 >> 1)] =
                __floats2half2_rn(acc[n][2] * dv8, acc[n][3] * dv8);
    }
}

// ---------------- CSR aggregation (fp16 gather, fp32 accumulate, fp16 out) -----
// 8 threads per node; thread owns 8 consecutive features (uint4 = 16B).
// Edge loop batched 4-wide: 4 indices loaded, then 4 row-gathers in flight.
__device__ __forceinline__ void acc_row(float* a, uint4 r) {
    const __half2* p = (const __half2*)&r;
    #pragma unroll
    for (int i = 0; i < 4; i++) {
        float2 f = __half22float2(p[i]);
        a[2 * i] += f.x; a[2 * i + 1] += f.y;
    }
}

__global__ void k_aggregate() {
    int idx = blockIdx.x * blockDim.x + threadIdx.x;   // over N*8
    if (idx >= N_NODES * 8) return;
    int node = idx >> 3;
    int q = idx & 7;
    const uint4* h4 = (const uint4*)g_hH;

    float a0[8], a1[8], a2[8], a3[8];
    #pragma unroll
    for (int i = 0; i < 8; i++) { a0[i] = 0.f; a1[i] = 0.f; a2[i] = 0.f; a3[i] = 0.f; }
    acc_row(a0, h4[(size_t)node * 8 + q]);   // self

    int e = g_rowoff[node], e1 = g_rowoff[node + 1];
    for (; e + 4 <= e1; e += 4) {
        int s0 = __ldg(&g_csr[e]);
        int s1 = __ldg(&g_csr[e + 1]);
        int s2 = __ldg(&g_csr[e + 2]);
        int s3 = __ldg(&g_csr[e + 3]);
        uint4 r0 = h4[(size_t)s0 * 8 + q];
        uint4 r1 = h4[(size_t)s1 * 8 + q];
        uint4 r2 = h4[(size_t)s2 * 8 + q];
        uint4 r3 = h4[(size_t)s3 * 8 + q];
        acc_row(a0, r0);
        acc_row(a1, r1);
        acc_row(a2, r2);
        acc_row(a3, r3);
    }
    if (e + 2 <= e1) {
        int s0 = __ldg(&g_csr[e]);
        int s1 = __ldg(&g_csr[e + 1]);
        uint4 r0 = h4[(size_t)s0 * 8 + q];
        uint4 r1 = h4[(size_t)s1 * 8 + q];
        acc_row(a0, r0);
        acc_row(a1, r1);
        e += 2;
    }
    if (e < e1) {
        int s0 = __ldg(&g_csr[e]);
        acc_row(a0, h4[(size_t)s0 * 8 + q]);
    }

    float dv = g_dinv[node];
    uint4 o;
    __half2* po = (__half2*)&o;
    #pragma unroll
    for (int i = 0; i < 4; i++)
        po[i] = __floats2half2_rn(
            (a0[2 * i] + a1[2 * i] + a2[2 * i] + a3[2 * i]) * dv,
            (a0[2 * i + 1] + a1[2 * i + 1] + a2[2 * i + 1] + a3[2 * i + 1]) * dv);
    ((uint4*)g_aggH)[idx] = o;
}

// ---------------- attention + pooling + final linear ---------------------------
__global__ void k_attn(const float* __restrict__ Wa, const float* __restrict__ v,
                       const float* __restrict__ Wl, const float* __restrict__ bl,
                       const float* __restrict__ b3,
                       float* __restrict__ out, float* __restrict__ lw) {
    __shared__ float sWaT[64 * 68];
    __shared__ float sWl[128 * 32];
    __shared__ float sV[64];
    __shared__ float sBl[32];
    __shared__ float sB3[64];
    __shared__ float sH[8][LEADS * 64];
    __shared__ float sScore[8][LEADS];
    __shared__ float sPool[8][128];

    int tid = threadIdx.x;
    for (int i = tid; i < 4096; i += 256) {
        int k = i >> 6, c = i & 63;
        sWaT[c * 68 + k] = Wa[i];
        sWl[i] = Wl[i];
    }
    if (tid < 64) { sV[tid] = v[tid]; sB3[tid] = b3[tid]; }
    if (tid < 32) sBl[tid] = bl[tid];
    __syncthreads();

    int w = tid >> 5, lane = tid & 31;
    int g = blockIdx.x * 8 + w;
    if (g >= NUM_GRAPHS) return;

    float* hs = sH[w];
    const uint4* hg = (const uint4*)(g_aggH + (size_t)g * (LEADS * 64));  // 96 uint4
    #pragma unroll
    for (int j = 0; j < 3; j++) {
        int id = lane + 32 * j;      // 0..95
        uint4 u = hg[id];
        int lead = id >> 3;
        int fb = (id & 7) * 8;
        const __half2* p = (const __half2*)&u;
        #pragma unroll
        for (int i = 0; i < 4; i++) {
            float2 f = __half22float2(p[i]);
            hs[lead * 64 + fb + 2 * i]     = fmaxf(f.x + sB3[fb + 2 * i], 0.f);
            hs[lead * 64 + fb + 2 * i + 1] = fmaxf(f.y + sB3[fb + 2 * i + 1], 0.f);
        }
    }
    __syncwarp();

    unsigned long long e0a[LEADS], e1a[LEADS];
    #pragma unroll
    for (int l = 0; l < LEADS; l++) { e0a[l] = 0ULL; e1a[l] = 0ULL; }
    const float* w0base = sWaT + lane * 68;
    const float* w1base = sWaT + (lane + 32) * 68;
    #pragma unroll 4
    for (int k4 = 0; k4 < 16; k4++) {
        ulonglong2 w0 = *(const ulonglong2*)(w0base + k4 * 4);
        ulonglong2 w1 = *(const ulonglong2*)(w1base + k4 * 4);
        #pragma unroll
        for (int l = 0; l < LEADS; l++) {
            ulonglong2 a = *(const ulonglong2*)(hs + l * 64 + k4 * 4);
            fma2(e0a[l], a.x, w0.x); fma2(e0a[l], a.y, w0.y);
            fma2(e1a[l], a.x, w1.x); fma2(e1a[l], a.y, w1.y);
        }
    }
    float v0 = sV[lane], v1 = sV[lane + 32];
    #pragma unroll
    for (int l = 0; l < LEADS; l++) {
        float s = tanhf(hsum2(e0a[l])) * v0 + tanhf(hsum2(e1a[l])) * v1;
        #pragma unroll
        for (int o = 16; o > 0; o >>= 1) s += __shfl_xor_sync(0xffffffff, s, o);
        if (lane == 0) sScore[w][l] = s;
    }
    __syncwarp();

    float sc[LEADS];
    #pragma unroll
    for (int l = 0; l < LEADS; l++) sc[l] = sScore[w][l];
    float m = sc[0];
    #pragma unroll
    for (int l = 1; l < LEADS; l++) m = fmaxf(m, sc[l]);
    float sum = 0.f;
    #pragma unroll
    for (int l = 0; l < LEADS; l++) { sc[l] = expf(sc[l] - m); sum += sc[l]; }
    float inv = 1.f / sum;
    #pragma unroll
    for (int l = 0; l < LEADS; l++) sc[l] *= inv;
    if (lane < LEADS) lw[(size_t)g * LEADS + lane] = sc[lane];

    #pragma unroll
    for (int half = 0; half < 2; half++) {
        int f = lane + 32 * half;
        float mx = -1e30f, sm = 0.f;
        #pragma unroll
        for (int l = 0; l < LEADS; l++) {
            float val = hs[l * 64 + f] * sc[l];
            mx = fmaxf(mx, val);
            sm += val;
        }
        sPool[w][f] = mx;
        sPool[w][64 + f] = sm * (1.f / 12.f);
    }
    __syncwarp();

    float acc = sBl[lane];
    #pragma unroll 16
    for (int f = 0; f < 128; f++) acc += sPool[w][f] * sWl[f * 32 + lane];
    out[(size_t)g * 32 + lane] = fmaxf(acc, 0.f);
}

// ---------------- launch --------------------------------------------------------
extern "C" void kernel_launch(void* const* d_in, const int* in_sizes, int n_in,
                              void* d_out, int out_size) {
    const float* x    = (const float*)d_in[0];
    const int*   ei   = (const int*)d_in[1];
    const int*   srcp = ei;
    const int*   dstp = ei + N_EDGES;
    const float* W1 = (const float*)d_in[3];
    const float* b1 = (const float*)d_in[4];
    const float* W2 = (const float*)d_in[5];
    const float* b2 = (const float*)d_in[6];
    const float* W3 = (const float*)d_in[7];
    const float* b3 = (const float*)d_in[8];
    const float* Wa = (const float*)d_in[9];
    const float* vv = (const float*)d_in[10];
    const float* Wl = (const float*)d_in[11];
    const float* bl = (const float*)d_in[12];

    float* out = (float*)d_out;                                  // [G,32]
    float* lw  = (float*)d_out + (size_t)NUM_GRAPHS * OUT_DIM;   // [G,12]

    __half* hp;  cudaGetSymbolAddress((void**)&hp,  g_hH);
    __half* ap;  cudaGetSymbolAddress((void**)&ap,  g_aggH);

    const int SM1 = (2 * 128 + 2 * 64) * (128 + 8) * 2;   // 104448 B
    const int SM2 = (2 * 128 + 2 * 64) * (64 + 8) * 2;    //  55296 B
    cudaFuncSetAttribute(k_gemm_mma<128, false, false>, cudaFuncAttributeMaxDynamicSharedMemorySize, SM1);
    cudaFuncSetAttribute(k_gemm_mma<64, true, true>,   cudaFuncAttributeMaxDynamicSharedMemorySize, SM2);

    const int T = 256;
    const int gN = (N_NODES + T - 1) / T;
    const int gE = (N_EDGES + T - 1) / T;
    const int GRID = (N_NODES + 127) / 128;
    const int AGG_GRID = (N_NODES * 8 + T - 1) / T;

    // launches 1-3
    k_deg_zero<<<gN, T>>>();
    k_deg_count<<<gE, T>>>(dstp);
    k_dinv<<<gN, T>>>();

    // launch 4 (ncu-profiled slot): tensor-core layer-1 GEMM
    k_gemm_mma<128, false, false><<<GRID, 256, SM1>>>(x, W1, nullptr, hp);

    // CSR build
    k_scan1<<<SCAN_NB, 1024>>>();
    k_scan2<<<1, 1024>>>();
    k_scan3<<<(N_NODES + 1023) / 1024, 1024>>>();
    k_place<<<gE, T>>>(srcp, dstp);

    k_aggregate<<<AGG_GRID, T>>>();
    k_gemm_mma<64, true, true><<<GRID, 256, SM2>>>(ap, W2, b1, hp);
    k_aggregate<<<AGG_GRID, T>>>();
    k_gemm_mma<64, true, true><<<GRID, 256, SM2>>>(ap, W3, b2, hp);
    k_aggregate<<<AGG_GRID, T>>>();

    k_attn<<<(NUM_GRAPHS + 7) / 8, 256>>>(Wa, vv, Wl, bl, b3, out, lw);
}

// round 12
// speedup vs baseline: 1.2893x; 1.0196x over previous
#include <cuda_runtime.h>
#include <cuda_fp16.h>
#include <cuda_bf16.h>

#define N_NODES 600000
#define N_EDGES 2400000
#define LEADS 12
#define NUM_GRAPHS 50000
#define F_IN 128
#define HDIM 64
#define OUT_DIM 32

#define SCAN_NB 586   // ceil(600000/1024)

// ---------------- packed fp32x2 FMA (used in attention) ------------------------
__device__ __forceinline__ void fma2(unsigned long long& d,
                                     unsigned long long a,
                                     unsigned long long b) {
    asm("fma.rn.f32x2 %0, %1, %2, %0;" : "+l"(d) : "l"(a), "l"(b));
}
__device__ __forceinline__ float hsum2(unsigned long long d) {
    float lo = __uint_as_float((unsigned int)(d & 0xffffffffULL));
    float hi = __uint_as_float((unsigned int)(d >> 32));
    return lo + hi;
}

// ---------------- mma m16n8k16, fp32 accumulate ---------------------------------
__device__ __forceinline__ void mma_bf16(float* c, const unsigned* a,
                                         unsigned b0, unsigned b1) {
    asm volatile(
        "mma.sync.aligned.m16n8k16.row.col.f32.bf16.bf16.f32 "
        "{%0,%1,%2,%3}, {%4,%5,%6,%7}, {%8,%9}, {%0,%1,%2,%3};"
        : "+f"(c[0]), "+f"(c[1]), "+f"(c[2]), "+f"(c[3])
        : "r"(a[0]), "r"(a[1]), "r"(a[2]), "r"(a[3]), "r"(b0), "r"(b1));
}
__device__ __forceinline__ void mma_f16(float* c, const unsigned* a,
                                        unsigned b0, unsigned b1) {
    asm volatile(
        "mma.sync.aligned.m16n8k16.row.col.f32.f16.f16.f32 "
        "{%0,%1,%2,%3}, {%4,%5,%6,%7}, {%8,%9}, {%0,%1,%2,%3};"
        : "+f"(c[0]), "+f"(c[1]), "+f"(c[2]), "+f"(c[3])
        : "r"(a[0]), "r"(a[1]), "r"(a[2]), "r"(a[3]), "r"(b0), "r"(b1));
}

// ---------------- scratch (device globals) ------------------------------------
__device__ __half g_hH  [(size_t)N_NODES * HDIM];  // GEMM output (gather source)
__device__ __half g_aggH[(size_t)N_NODES * HDIM];  // aggregated layer output
__device__ float  g_dinv[N_NODES];
__device__ int    g_deg[N_NODES];
__device__ int    g_rowoff[N_NODES + 1];
__device__ int    g_cursor[N_NODES];
__device__ int    g_csr[N_EDGES];
__device__ int    g_bsum[SCAN_NB];
__device__ int    g_boff[SCAN_NB];

// ---------------- degree / CSR build -------------------------------------------
__global__ void k_deg_zero() {
    int i = blockIdx.x * blockDim.x + threadIdx.x;
    if (i < N_NODES) g_deg[i] = 0;
}

__global__ void k_deg_count(const int* __restrict__ dst) {
    int e = blockIdx.x * blockDim.x + threadIdx.x;
    if (e < N_EDGES) atomicAdd(&g_deg[dst[e]], 1);
}

__global__ void k_dinv() {
    int i = blockIdx.x * blockDim.x + threadIdx.x;
    if (i < N_NODES) g_dinv[i] = rsqrtf((float)(g_deg[i] + 1));
}

__global__ void k_scan1() {
    __shared__ int sh[1024];
    int i = blockIdx.x * 1024 + threadIdx.x;
    int v = (i < N_NODES) ? g_deg[i] : 0;
    sh[threadIdx.x] = v;
    __syncthreads();
    #pragma unroll
    for (int off = 1; off < 1024; off <<= 1) {
        int t = 0;
        if (threadIdx.x >= off) t = sh[threadIdx.x - off];
        __syncthreads();
        if (threadIdx.x >= off) sh[threadIdx.x] += t;
        __syncthreads();
    }
    if (i < N_NODES) g_rowoff[i] = sh[threadIdx.x] - v;   // exclusive
    if (threadIdx.x == 1023) g_bsum[blockIdx.x] = sh[1023];
}

__global__ void k_scan2() {
    __shared__ int sh[1024];
    int v = (threadIdx.x < SCAN_NB) ? g_bsum[threadIdx.x] : 0;
    sh[threadIdx.x] = v;
    __syncthreads();
    #pragma unroll
    for (int off = 1; off < 1024; off <<= 1) {
        int t = 0;
        if (threadIdx.x >= off) t = sh[threadIdx.x - off];
        __syncthreads();
        if (threadIdx.x >= off) sh[threadIdx.x] += t;
        __syncthreads();
    }
    if (threadIdx.x < SCAN_NB) g_boff[threadIdx.x] = sh[threadIdx.x] - v;
}

__global__ void k_scan3() {
    int i = blockIdx.x * blockDim.x + threadIdx.x;
    if (i < N_NODES) {
        int ro = g_rowoff[i] + g_boff[i >> 10];
        g_rowoff[i] = ro;
        g_cursor[i] = ro;
    }
    if (i == 0) g_rowoff[N_NODES] = N_EDGES;
}

__global__ void k_place(const int* __restrict__ src, const int* __restrict__ dst) {
    int e = blockIdx.x * blockDim.x + threadIdx.x;
    if (e < N_EDGES) {
        int pos = atomicAdd(&g_cursor[dst[e]], 1);
        g_csr[pos] = src[e];
    }
}

// ---------------- layer-1 GEMM (fp32 input): bf16 split, 3 HMMA ----------------
__global__ void k_gemm1(const float* __restrict__ Ain, const float* __restrict__ W,
                        __half* __restrict__ C) {
    constexpr int K = 128, BM = 128;
    constexpr int KP = K + 8;
    constexpr int KQ = K / 4;
    constexpr int NIT = BM * KQ / 256;   // 16
    extern __shared__ char smem_raw[];
    __nv_bfloat16* sAhi = (__nv_bfloat16*)smem_raw;            // [BM][KP]
    __nv_bfloat16* sAlo = sAhi + BM * KP;                      // [BM][KP]
    __nv_bfloat16* sWhi = sAlo + BM * KP;                      // [64][KP] (transposed)
    __nv_bfloat16* sWlo = sWhi + 64 * KP;                      // [64][KP]

    const int tid = threadIdx.x;
    const int r0 = blockIdx.x * BM;

    for (int i = tid; i < K * 64; i += 256) {
        int k = i >> 6, c = i & 63;
        float w = W[i];
        __nv_bfloat16 hi = __float2bfloat16_rn(w);
        sWhi[c * KP + k] = hi;
        sWlo[c * KP + k] = __float2bfloat16_rn(w - __bfloat162float(hi));
    }

    #pragma unroll
    for (int base = 0; base < NIT; base += 8) {
        float av[8][4];
        #pragma unroll
        for (int j = 0; j < 8; j++) {
            int i = tid + (base + j) * 256;
            int row = i / KQ, kq = i - row * KQ;
            av[j][0] = 0.f; av[j][1] = 0.f; av[j][2] = 0.f; av[j][3] = 0.f;
            if (r0 + row < N_NODES) {
                float4 a = __ldg(((const float4*)Ain) + (size_t)(r0 + row) * KQ + kq);
                av[j][0] = a.x; av[j][1] = a.y; av[j][2] = a.z; av[j][3] = a.w;
            }
        }
        #pragma unroll
        for (int j = 0; j < 8; j++) {
            int i = tid + (base + j) * 256;
            int row = i / KQ, kq = i - row * KQ;
            __nv_bfloat16 hv[4], lv[4];
            #pragma unroll
            for (int q = 0; q < 4; q++) {
                hv[q] = __float2bfloat16_rn(av[j][q]);
                lv[q] = __float2bfloat16_rn(av[j][q] - __bfloat162float(hv[q]));
            }
            __nv_bfloat162* ph = (__nv_bfloat162*)(sAhi + row * KP + kq * 4);
            __nv_bfloat162* pl = (__nv_bfloat162*)(sAlo + row * KP + kq * 4);
            ph[0] = __nv_bfloat162(hv[0], hv[1]);
            ph[1] = __nv_bfloat162(hv[2], hv[3]);
            pl[0] = __nv_bfloat162(lv[0], lv[1]);
            pl[1] = __nv_bfloat162(lv[2], lv[3]);
        }
    }
    __syncthreads();

    const int warp = tid >> 5;
    const int lane = tid & 31;
    const int g  = lane >> 2;
    const int t2 = (lane & 3) * 2;
    const int wrow = warp * 16;

    float acc[8][4];
    #pragma unroll
    for (int n = 0; n < 8; n++)
        #pragma unroll
        for (int c = 0; c < 4; c++) acc[n][c] = 0.f;

    #pragma unroll
    for (int kb = 0; kb < K / 16; kb++) {
        const int kO = kb * 16 + t2;
        unsigned ahi[4], alo[4];
        {
            int rA = wrow + g;
            const unsigned* pH0 = (const unsigned*)(sAhi + rA * KP + kO);
            const unsigned* pH8 = (const unsigned*)(sAhi + (rA + 8) * KP + kO);
            const unsigned* pL0 = (const unsigned*)(sAlo + rA * KP + kO);
            const unsigned* pL8 = (const unsigned*)(sAlo + (rA + 8) * KP + kO);
            ahi[0] = pH0[0]; ahi[1] = pH8[0]; ahi[2] = pH0[4]; ahi[3] = pH8[4];
            alo[0] = pL0[0]; alo[1] = pL8[0]; alo[2] = pL0[4]; alo[3] = pL8[4];
        }
        #pragma unroll
        for (int n = 0; n < 8; n++) {
            int rB = n * 8 + g;
            const unsigned* qH = (const unsigned*)(sWhi + rB * KP + kO);
            const unsigned* qL = (const unsigned*)(sWlo + rB * KP + kO);
            unsigned bh0 = qH[0], bh1 = qH[4];
            unsigned bl0 = qL[0], bl1 = qL[4];
            mma_bf16(acc[n], ahi, bh0, bh1);
            mma_bf16(acc[n], ahi, bl0, bl1);
            mma_bf16(acc[n], alo, bh0, bh1);
        }
    }

    __half2* C2 = (__half2*)C;
    int r  = r0 + wrow + g;
    int r8 = r + 8;
    float dv  = (r  < N_NODES) ? g_dinv[r]  : 0.f;
    float dv8 = (r8 < N_NODES) ? g_dinv[r8] : 0.f;
    #pragma unroll
    for (int n = 0; n < 8; n++) {
        if (r < N_NODES)
            C2[(size_t)r * 32 + n * 4 + (t2 >> 1)] =
                __floats2half2_rn(acc[n][0] * dv, acc[n][1] * dv);
        if (r8 < N_NODES)
            C2[(size_t)r8 * 32 + n * 4 + (t2 >> 1)] =
                __floats2half2_rn(acc[n][2] * dv8, acc[n][3] * dv8);
    }
}

// ---------------- layers 2/3 GEMM (fp16 input): native fp16 MMA, W hi/lo -------
// A = relu(agg + bias) rounded to fp16 (single smem buffer); 2 HMMA per k-block.
__global__ void k_gemm_f16(const __half* __restrict__ Ain, const float* __restrict__ W,
                           const float* __restrict__ bias, __half* __restrict__ C) {
    constexpr int K = 64, BM = 128;
    constexpr int KP = K + 8;
    constexpr int KQ = K / 4;
    constexpr int NIT = BM * KQ / 256;   // 8
    extern __shared__ char smem_raw[];
    __half* sA   = (__half*)smem_raw;        // [BM][KP]
    __half* sWhi = sA + BM * KP;             // [64][KP] (transposed)
    __half* sWlo = sWhi + 64 * KP;           // [64][KP]

    const int tid = threadIdx.x;
    const int r0 = blockIdx.x * BM;

    for (int i = tid; i < K * 64; i += 256) {
        int k = i >> 6, c = i & 63;
        float w = W[i];
        __half hi = __float2half_rn(w);
        sWhi[c * KP + k] = hi;
        sWlo[c * KP + k] = __float2half_rn(w - __half2float(hi));
    }

    const float4* B4 = (const float4*)bias;
    {
        float av[NIT][4];
        #pragma unroll
        for (int j = 0; j < NIT; j++) {
            int i = tid + j * 256;
            int row = i / KQ, kq = i - row * KQ;
            av[j][0] = 0.f; av[j][1] = 0.f; av[j][2] = 0.f; av[j][3] = 0.f;
            if (r0 + row < N_NODES) {
                uint2 u = __ldg(((const uint2*)Ain) + (size_t)(r0 + row) * KQ + kq);
                float2 f0 = __half22float2(*(const __half2*)&u.x);
                float2 f1 = __half22float2(*(const __half2*)&u.y);
                av[j][0] = f0.x; av[j][1] = f0.y; av[j][2] = f1.x; av[j][3] = f1.y;
            }
        }
        #pragma unroll
        for (int j = 0; j < NIT; j++) {
            int i = tid + j * 256;
            int row = i / KQ, kq = i - row * KQ;
            float4 b = B4[kq];
            float x0 = fmaxf(av[j][0] + b.x, 0.f);
            float x1 = fmaxf(av[j][1] + b.y, 0.f);
            float x2 = fmaxf(av[j][2] + b.z, 0.f);
            float x3 = fmaxf(av[j][3] + b.w, 0.f);
            __half2* pa = (__half2*)(sA + row * KP + kq * 4);
            pa[0] = __floats2half2_rn(x0, x1);
            pa[1] = __floats2half2_rn(x2, x3);
        }
    }
    __syncthreads();

    const int warp = tid >> 5;
    const int lane = tid & 31;
    const int g  = lane >> 2;
    const int t2 = (lane & 3) * 2;
    const int wrow = warp * 16;

    float acc[8][4];
    #pragma unroll
    for (int n = 0; n < 8; n++)
        #pragma unroll
        for (int c = 0; c < 4; c++) acc[n][c] = 0.f;

    #pragma unroll
    for (int kb = 0; kb < K / 16; kb++) {
        const int kO = kb * 16 + t2;
        unsigned a[4];
        {
            int rA = wrow + g;
            const unsigned* p0 = (const unsigned*)(sA + rA * KP + kO);
            const unsigned* p8 = (const unsigned*)(sA + (rA + 8) * KP + kO);
            a[0] = p0[0]; a[1] = p8[0]; a[2] = p0[4]; a[3] = p8[4];
        }
        #pragma unroll
        for (int n = 0; n < 8; n++) {
            int rB = n * 8 + g;
            const unsigned* qH = (const unsigned*)(sWhi + rB * KP + kO);
            const unsigned* qL = (const unsigned*)(sWlo + rB * KP + kO);
            unsigned bh0 = qH[0], bh1 = qH[4];
            unsigned bl0 = qL[0], bl1 = qL[4];
            mma_f16(acc[n], a, bh0, bh1);
            mma_f16(acc[n], a, bl0, bl1);
        }
    }

    __half2* C2 = (__half2*)C;
    int r  = r0 + wrow + g;
    int r8 = r + 8;
    float dv  = (r  < N_NODES) ? g_dinv[r]  : 0.f;
    float dv8 = (r8 < N_NODES) ? g_dinv[r8] : 0.f;
    #pragma unroll
    for (int n = 0; n < 8; n++) {
        if (r < N_NODES)
            C2[(size_t)r * 32 + n * 4 + (t2 >> 1)] =
                __floats2half2_rn(acc[n][0] * dv, acc[n][1] * dv);
        if (r8 < N_NODES)
            C2[(size_t)r8 * 32 + n * 4 + (t2 >> 1)] =
                __floats2half2_rn(acc[n][2] * dv8, acc[n][3] * dv8);
    }
}

// ---------------- CSR aggregation (fp16 gather, fp32 accumulate, fp16 out) -----
// 8 threads per node; thread owns 8 consecutive features (uint4 = 16B).
// Edge loop batched 4-wide: 4 indices loaded, then 4 row-gathers in flight.
__device__ __forceinline__ void acc_row(float* a, uint4 r) {
    const __half2* p = (const __half2*)&r;
    #pragma unroll
    for (int i = 0; i < 4; i++) {
        float2 f = __half22float2(p[i]);
        a[2 * i] += f.x; a[2 * i + 1] += f.y;
    }
}

__global__ void k_aggregate() {
    int idx = blockIdx.x * blockDim.x + threadIdx.x;   // over N*8
    if (idx >= N_NODES * 8) return;
    int node = idx >> 3;
    int q = idx & 7;
    const uint4* h4 = (const uint4*)g_hH;

    float a0[8], a1[8], a2[8], a3[8];
    #pragma unroll
    for (int i = 0; i < 8; i++) { a0[i] = 0.f; a1[i] = 0.f; a2[i] = 0.f; a3[i] = 0.f; }
    acc_row(a0, h4[(size_t)node * 8 + q]);   // self

    int e = g_rowoff[node], e1 = g_rowoff[node + 1];
    for (; e + 4 <= e1; e += 4) {
        int s0 = __ldg(&g_csr[e]);
        int s1 = __ldg(&g_csr[e + 1]);
        int s2 = __ldg(&g_csr[e + 2]);
        int s3 = __ldg(&g_csr[e + 3]);
        uint4 r0 = h4[(size_t)s0 * 8 + q];
        uint4 r1 = h4[(size_t)s1 * 8 + q];
        uint4 r2 = h4[(size_t)s2 * 8 + q];
        uint4 r3 = h4[(size_t)s3 * 8 + q];
        acc_row(a0, r0);
        acc_row(a1, r1);
        acc_row(a2, r2);
        acc_row(a3, r3);
    }
    if (e + 2 <= e1) {
        int s0 = __ldg(&g_csr[e]);
        int s1 = __ldg(&g_csr[e + 1]);
        uint4 r0 = h4[(size_t)s0 * 8 + q];
        uint4 r1 = h4[(size_t)s1 * 8 + q];
        acc_row(a0, r0);
        acc_row(a1, r1);
        e += 2;
    }
    if (e < e1) {
        int s0 = __ldg(&g_csr[e]);
        acc_row(a0, h4[(size_t)s0 * 8 + q]);
    }

    float dv = g_dinv[node];
    uint4 o;
    __half2* po = (__half2*)&o;
    #pragma unroll
    for (int i = 0; i < 4; i++)
        po[i] = __floats2half2_rn(
            (a0[2 * i] + a1[2 * i] + a2[2 * i] + a3[2 * i]) * dv,
            (a0[2 * i + 1] + a1[2 * i + 1] + a2[2 * i + 1] + a3[2 * i + 1]) * dv);
    ((uint4*)g_aggH)[idx] = o;
}

// ---------------- attention + pooling + final linear ---------------------------
__global__ void k_attn(const float* __restrict__ Wa, const float* __restrict__ v,
                       const float* __restrict__ Wl, const float* __restrict__ bl,
                       const float* __restrict__ b3,
                       float* __restrict__ out, float* __restrict__ lw) {
    __shared__ float sWaT[64 * 68];
    __shared__ float sWl[128 * 32];
    __shared__ float sV[64];
    __shared__ float sBl[32];
    __shared__ float sB3[64];
    __shared__ float sH[8][LEADS * 64];
    __shared__ float sScore[8][LEADS];
    __shared__ float sPool[8][128];

    int tid = threadIdx.x;
    for (int i = tid; i < 4096; i += 256) {
        int k = i >> 6, c = i & 63;
        sWaT[c * 68 + k] = Wa[i];
        sWl[i] = Wl[i];
    }
    if (tid < 64) { sV[tid] = v[tid]; sB3[tid] = b3[tid]; }
    if (tid < 32) sBl[tid] = bl[tid];
    __syncthreads();

    int w = tid >> 5, lane = tid & 31;
    int g = blockIdx.x * 8 + w;
    if (g >= NUM_GRAPHS) return;

    float* hs = sH[w];
    const uint4* hg = (const uint4*)(g_aggH + (size_t)g * (LEADS * 64));  // 96 uint4
    #pragma unroll
    for (int j = 0; j < 3; j++) {
        int id = lane + 32 * j;      // 0..95
        uint4 u = hg[id];
        int lead = id >> 3;
        int fb = (id & 7) * 8;
        const __half2* p = (const __half2*)&u;
        #pragma unroll
        for (int i = 0; i < 4; i++) {
            float2 f = __half22float2(p[i]);
            hs[lead * 64 + fb + 2 * i]     = fmaxf(f.x + sB3[fb + 2 * i], 0.f);
            hs[lead * 64 + fb + 2 * i + 1] = fmaxf(f.y + sB3[fb + 2 * i + 1], 0.f);
        }
    }
    __syncwarp();

    unsigned long long e0a[LEADS], e1a[LEADS];
    #pragma unroll
    for (int l = 0; l < LEADS; l++) { e0a[l] = 0ULL; e1a[l] = 0ULL; }
    const float* w0base = sWaT + lane * 68;
    const float* w1base = sWaT + (lane + 32) * 68;
    #pragma unroll 4
    for (int k4 = 0; k4 < 16; k4++) {
        ulonglong2 w0 = *(const ulonglong2*)(w0base + k4 * 4);
        ulonglong2 w1 = *(const ulonglong2*)(w1base + k4 * 4);
        #pragma unroll
        for (int l = 0; l < LEADS; l++) {
            ulonglong2 a = *(const ulonglong2*)(hs + l * 64 + k4 * 4);
            fma2(e0a[l], a.x, w0.x); fma2(e0a[l], a.y, w0.y);
            fma2(e1a[l], a.x, w1.x); fma2(e1a[l], a.y, w1.y);
        }
    }
    float v0 = sV[lane], v1 = sV[lane + 32];
    #pragma unroll
    for (int l = 0; l < LEADS; l++) {
        float s = tanhf(hsum2(e0a[l])) * v0 + tanhf(hsum2(e1a[l])) * v1;
        #pragma unroll
        for (int o = 16; o > 0; o >>= 1) s += __shfl_xor_sync(0xffffffff, s, o);
        if (lane == 0) sScore[w][l] = s;
    }
    __syncwarp();

    float sc[LEADS];
    #pragma unroll
    for (int l = 0; l < LEADS; l++) sc[l] = sScore[w][l];
    float m = sc[0];
    #pragma unroll
    for (int l = 1; l < LEADS; l++) m = fmaxf(m, sc[l]);
    float sum = 0.f;
    #pragma unroll
    for (int l = 0; l < LEADS; l++) { sc[l] = expf(sc[l] - m); sum += sc[l]; }
    float inv = 1.f / sum;
    #pragma unroll
    for (int l = 0; l < LEADS; l++) sc[l] *= inv;
    if (lane < LEADS) lw[(size_t)g * LEADS + lane] = sc[lane];

    #pragma unroll
    for (int half = 0; half < 2; half++) {
        int f = lane + 32 * half;
        float mx = -1e30f, sm = 0.f;
        #pragma unroll
        for (int l = 0; l < LEADS; l++) {
            float val = hs[l * 64 + f] * sc[l];
            mx = fmaxf(mx, val);
            sm += val;
        }
        sPool[w][f] = mx;
        sPool[w][64 + f] = sm * (1.f / 12.f);
    }
    __syncwarp();

    float acc = sBl[lane];
    #pragma unroll 16
    for (int f = 0; f < 128; f++) acc += sPool[w][f] * sWl[f * 32 + lane];
    out[(size_t)g * 32 + lane] = fmaxf(acc, 0.f);
}

// ---------------- launch --------------------------------------------------------
extern "C" void kernel_launch(void* const* d_in, const int* in_sizes, int n_in,
                              void* d_out, int out_size) {
    const float* x    = (const float*)d_in[0];
    const int*   ei   = (const int*)d_in[1];
    const int*   srcp = ei;
    const int*   dstp = ei + N_EDGES;
    const float* W1 = (const float*)d_in[3];
    const float* b1 = (const float*)d_in[4];
    const float* W2 = (const float*)d_in[5];
    const float* b2 = (const float*)d_in[6];
    const float* W3 = (const float*)d_in[7];
    const float* b3 = (const float*)d_in[8];
    const float* Wa = (const float*)d_in[9];
    const float* vv = (const float*)d_in[10];
    const float* Wl = (const float*)d_in[11];
    const float* bl = (const float*)d_in[12];

    float* out = (float*)d_out;                                  // [G,32]
    float* lw  = (float*)d_out + (size_t)NUM_GRAPHS * OUT_DIM;   // [G,12]

    __half* hp;  cudaGetSymbolAddress((void**)&hp,  g_hH);
    __half* ap;  cudaGetSymbolAddress((void**)&ap,  g_aggH);

    const int SM1 = (2 * 128 + 2 * 64) * (128 + 8) * 2;   // 104448 B
    const int SM2 = (128 + 2 * 64) * (64 + 8) * 2;        //  36864 B
    cudaFuncSetAttribute(k_gemm1,    cudaFuncAttributeMaxDynamicSharedMemorySize, SM1);
    cudaFuncSetAttribute(k_gemm_f16, cudaFuncAttributeMaxDynamicSharedMemorySize, SM2);

    const int T = 256;
    const int gN = (N_NODES + T - 1) / T;
    const int gE = (N_EDGES + T - 1) / T;
    const int GRID = (N_NODES + 127) / 128;
    const int AGG_GRID = (N_NODES * 8 + T - 1) / T;

    // launches 1-3
    k_deg_zero<<<gN, T>>>();
    k_deg_count<<<gE, T>>>(dstp);
    k_dinv<<<gN, T>>>();

    // launch 4 (ncu-profiled slot): tensor-core layer-1 GEMM
    k_gemm1<<<GRID, 256, SM1>>>(x, W1, hp);

    // CSR build
    k_scan1<<<SCAN_NB, 1024>>>();
    k_scan2<<<1, 1024>>>();
    k_scan3<<<(N_NODES + 1023) / 1024, 1024>>>();
    k_place<<<gE, T>>>(srcp, dstp);

    k_aggregate<<<AGG_GRID, T>>>();
    k_gemm_f16<<<GRID, 256, SM2>>>(ap, W2, b1, hp);
    k_aggregate<<<AGG_GRID, T>>>();
    k_gemm_f16<<<GRID, 256, SM2>>>(ap, W3, b2, hp);
    k_aggregate<<<AGG_GRID, T>>>();

    k_attn<<<(NUM_GRAPHS + 7) / 8, 256>>>(Wa, vv, Wl, bl, b3, out, lw);
}

// round 13
// speedup vs baseline: 1.3380x; 1.0377x over previous
#include <cuda_runtime.h>
#include <cuda_fp16.h>
#include <cuda_bf16.h>

#define N_NODES 600000
#define N_HALF  300000
#define N_EDGES 2400000
#define LEADS 12
#define NUM_GRAPHS 50000
#define F_IN 128
#define HDIM 64
#define OUT_DIM 32

#define SCAN_NB 586   // ceil(600000/1024)

// ---------------- packed fp32x2 FMA (used in attention) ------------------------
__device__ __forceinline__ void fma2(unsigned long long& d,
                                     unsigned long long a,
                                     unsigned long long b) {
    asm("fma.rn.f32x2 %0, %1, %2, %0;" : "+l"(d) : "l"(a), "l"(b));
}
__device__ __forceinline__ float hsum2(unsigned long long d) {
    float lo = __uint_as_float((unsigned int)(d & 0xffffffffULL));
    float hi = __uint_as_float((unsigned int)(d >> 32));
    return lo + hi;
}

// ---------------- mma m16n8k16, fp32 accumulate ---------------------------------
__device__ __forceinline__ void mma_bf16(float* c, const unsigned* a,
                                         unsigned b0, unsigned b1) {
    asm volatile(
        "mma.sync.aligned.m16n8k16.row.col.f32.bf16.bf16.f32 "
        "{%0,%1,%2,%3}, {%4,%5,%6,%7}, {%8,%9}, {%0,%1,%2,%3};"
        : "+f"(c[0]), "+f"(c[1]), "+f"(c[2]), "+f"(c[3])
        : "r"(a[0]), "r"(a[1]), "r"(a[2]), "r"(a[3]), "r"(b0), "r"(b1));
}
__device__ __forceinline__ void mma_f16(float* c, const unsigned* a,
                                        unsigned b0, unsigned b1) {
    asm volatile(
        "mma.sync.aligned.m16n8k16.row.col.f32.f16.f16.f32 "
        "{%0,%1,%2,%3}, {%4,%5,%6,%7}, {%8,%9}, {%0,%1,%2,%3};"
        : "+f"(c[0]), "+f"(c[1]), "+f"(c[2]), "+f"(c[3])
        : "r"(a[0]), "r"(a[1]), "r"(a[2]), "r"(a[3]), "r"(b0), "r"(b1));
}

// ---------------- scratch (device globals) ------------------------------------
__device__ __half g_hH  [(size_t)N_NODES * HDIM];  // GEMM output (gather source)
__device__ __half g_aggH[(size_t)N_NODES * HDIM];  // aggregated layer output
__device__ float  g_dinv[N_NODES];
__device__ int    g_deg[N_NODES];
__device__ int    g_rowoff[N_NODES + 1];
__device__ int    g_cursor[N_NODES];
__device__ int    g_csr[N_EDGES];
__device__ int    g_bsum[SCAN_NB];
__device__ int    g_boff[SCAN_NB];

// ---------------- degree / CSR build -------------------------------------------
__global__ void k_deg_zero() {
    int i = blockIdx.x * blockDim.x + threadIdx.x;
    if (i < N_NODES) g_deg[i] = 0;
}

__global__ void k_deg_count(const int* __restrict__ dst) {
    int e = blockIdx.x * blockDim.x + threadIdx.x;
    if (e < N_EDGES) atomicAdd(&g_deg[dst[e]], 1);
}

__global__ void k_dinv() {
    int i = blockIdx.x * blockDim.x + threadIdx.x;
    if (i < N_NODES) g_dinv[i] = rsqrtf((float)(g_deg[i] + 1));
}

__global__ void k_scan1() {
    __shared__ int sh[1024];
    int i = blockIdx.x * 1024 + threadIdx.x;
    int v = (i < N_NODES) ? g_deg[i] : 0;
    sh[threadIdx.x] = v;
    __syncthreads();
    #pragma unroll
    for (int off = 1; off < 1024; off <<= 1) {
        int t = 0;
        if (threadIdx.x >= off) t = sh[threadIdx.x - off];
        __syncthreads();
        if (threadIdx.x >= off) sh[threadIdx.x] += t;
        __syncthreads();
    }
    if (i < N_NODES) g_rowoff[i] = sh[threadIdx.x] - v;   // exclusive
    if (threadIdx.x == 1023) g_bsum[blockIdx.x] = sh[1023];
}

__global__ void k_scan2() {
    __shared__ int sh[1024];
    int v = (threadIdx.x < SCAN_NB) ? g_bsum[threadIdx.x] : 0;
    sh[threadIdx.x] = v;
    __syncthreads();
    #pragma unroll
    for (int off = 1; off < 1024; off <<= 1) {
        int t = 0;
        if (threadIdx.x >= off) t = sh[threadIdx.x - off];
        __syncthreads();
        if (threadIdx.x >= off) sh[threadIdx.x] += t;
        __syncthreads();
    }
    if (threadIdx.x < SCAN_NB) g_boff[threadIdx.x] = sh[threadIdx.x] - v;
}

__global__ void k_scan3() {
    int i = blockIdx.x * blockDim.x + threadIdx.x;
    if (i < N_NODES) {
        int ro = g_rowoff[i] + g_boff[i >> 10];
        g_rowoff[i] = ro;
        g_cursor[i] = ro;
    }
    if (i == 0) g_rowoff[N_NODES] = N_EDGES;
}

__global__ void k_place(const int* __restrict__ src, const int* __restrict__ dst) {
    int e = blockIdx.x * blockDim.x + threadIdx.x;
    if (e < N_EDGES) {
        int pos = atomicAdd(&g_cursor[dst[e]], 1);
        g_csr[pos] = src[e];
    }
}

// ---------------- layer-1 GEMM (fp32 input): bf16 split, 3 HMMA ----------------
__global__ void k_gemm1(const float* __restrict__ Ain, const float* __restrict__ W,
                        __half* __restrict__ C) {
    constexpr int K = 128, BM = 128;
    constexpr int KP = K + 8;
    constexpr int KQ = K / 4;
    constexpr int NIT = BM * KQ / 256;   // 16
    extern __shared__ char smem_raw[];
    __nv_bfloat16* sAhi = (__nv_bfloat16*)smem_raw;            // [BM][KP]
    __nv_bfloat16* sAlo = sAhi + BM * KP;                      // [BM][KP]
    __nv_bfloat16* sWhi = sAlo + BM * KP;                      // [64][KP] (transposed)
    __nv_bfloat16* sWlo = sWhi + 64 * KP;                      // [64][KP]

    const int tid = threadIdx.x;
    const int r0 = blockIdx.x * BM;

    for (int i = tid; i < K * 64; i += 256) {
        int k = i >> 6, c = i & 63;
        float w = W[i];
        __nv_bfloat16 hi = __float2bfloat16_rn(w);
        sWhi[c * KP + k] = hi;
        sWlo[c * KP + k] = __float2bfloat16_rn(w - __bfloat162float(hi));
    }

    #pragma unroll
    for (int base = 0; base < NIT; base += 8) {
        float av[8][4];
        #pragma unroll
        for (int j = 0; j < 8; j++) {
            int i = tid + (base + j) * 256;
            int row = i / KQ, kq = i - row * KQ;
            av[j][0] = 0.f; av[j][1] = 0.f; av[j][2] = 0.f; av[j][3] = 0.f;
            if (r0 + row < N_NODES) {
                float4 a = __ldg(((const float4*)Ain) + (size_t)(r0 + row) * KQ + kq);
                av[j][0] = a.x; av[j][1] = a.y; av[j][2] = a.z; av[j][3] = a.w;
            }
        }
        #pragma unroll
        for (int j = 0; j < 8; j++) {
            int i = tid + (base + j) * 256;
            int row = i / KQ, kq = i - row * KQ;
            __nv_bfloat16 hv[4], lv[4];
            #pragma unroll
            for (int q = 0; q < 4; q++) {
                hv[q] = __float2bfloat16_rn(av[j][q]);
                lv[q] = __float2bfloat16_rn(av[j][q] - __bfloat162float(hv[q]));
            }
            __nv_bfloat162* ph = (__nv_bfloat162*)(sAhi + row * KP + kq * 4);
            __nv_bfloat162* pl = (__nv_bfloat162*)(sAlo + row * KP + kq * 4);
            ph[0] = __nv_bfloat162(hv[0], hv[1]);
            ph[1] = __nv_bfloat162(hv[2], hv[3]);
            pl[0] = __nv_bfloat162(lv[0], lv[1]);
            pl[1] = __nv_bfloat162(lv[2], lv[3]);
        }
    }
    __syncthreads();

    const int warp = tid >> 5;
    const int lane = tid & 31;
    const int g  = lane >> 2;
    const int t2 = (lane & 3) * 2;
    const int wrow = warp * 16;

    float acc[8][4];
    #pragma unroll
    for (int n = 0; n < 8; n++)
        #pragma unroll
        for (int c = 0; c < 4; c++) acc[n][c] = 0.f;

    #pragma unroll
    for (int kb = 0; kb < K / 16; kb++) {
        const int kO = kb * 16 + t2;
        unsigned ahi[4], alo[4];
        {
            int rA = wrow + g;
            const unsigned* pH0 = (const unsigned*)(sAhi + rA * KP + kO);
            const unsigned* pH8 = (const unsigned*)(sAhi + (rA + 8) * KP + kO);
            const unsigned* pL0 = (const unsigned*)(sAlo + rA * KP + kO);
            const unsigned* pL8 = (const unsigned*)(sAlo + (rA + 8) * KP + kO);
            ahi[0] = pH0[0]; ahi[1] = pH8[0]; ahi[2] = pH0[4]; ahi[3] = pH8[4];
            alo[0] = pL0[0]; alo[1] = pL8[0]; alo[2] = pL0[4]; alo[3] = pL8[4];
        }
        #pragma unroll
        for (int n = 0; n < 8; n++) {
            int rB = n * 8 + g;
            const unsigned* qH = (const unsigned*)(sWhi + rB * KP + kO);
            const unsigned* qL = (const unsigned*)(sWlo + rB * KP + kO);
            unsigned bh0 = qH[0], bh1 = qH[4];
            unsigned bl0 = qL[0], bl1 = qL[4];
            mma_bf16(acc[n], ahi, bh0, bh1);
            mma_bf16(acc[n], ahi, bl0, bl1);
            mma_bf16(acc[n], alo, bh0, bh1);
        }
    }

    __half2* C2 = (__half2*)C;
    int r  = r0 + wrow + g;
    int r8 = r + 8;
    float dv  = (r  < N_NODES) ? g_dinv[r]  : 0.f;
    float dv8 = (r8 < N_NODES) ? g_dinv[r8] : 0.f;
    #pragma unroll
    for (int n = 0; n < 8; n++) {
        if (r < N_NODES)
            C2[(size_t)r * 32 + n * 4 + (t2 >> 1)] =
                __floats2half2_rn(acc[n][0] * dv, acc[n][1] * dv);
        if (r8 < N_NODES)
            C2[(size_t)r8 * 32 + n * 4 + (t2 >> 1)] =
                __floats2half2_rn(acc[n][2] * dv8, acc[n][3] * dv8);
    }
}

// ---------------- layers 2/3 GEMM (fp16 input): native fp16 MMA, W hi/lo -------
__global__ void k_gemm_f16(const __half* __restrict__ Ain, const float* __restrict__ W,
                           const float* __restrict__ bias, __half* __restrict__ C) {
    constexpr int K = 64, BM = 128;
    constexpr int KP = K + 8;
    constexpr int KQ = K / 4;
    constexpr int NIT = BM * KQ / 256;   // 8
    extern __shared__ char smem_raw[];
    __half* sA   = (__half*)smem_raw;        // [BM][KP]
    __half* sWhi = sA + BM * KP;             // [64][KP] (transposed)
    __half* sWlo = sWhi + 64 * KP;           // [64][KP]

    const int tid = threadIdx.x;
    const int r0 = blockIdx.x * BM;

    for (int i = tid; i < K * 64; i += 256) {
        int k = i >> 6, c = i & 63;
        float w = W[i];
        __half hi = __float2half_rn(w);
        sWhi[c * KP + k] = hi;
        sWlo[c * KP + k] = __float2half_rn(w - __half2float(hi));
    }

    const float4* B4 = (const float4*)bias;
    {
        float av[NIT][4];
        #pragma unroll
        for (int j = 0; j < NIT; j++) {
            int i = tid + j * 256;
            int row = i / KQ, kq = i - row * KQ;
            av[j][0] = 0.f; av[j][1] = 0.f; av[j][2] = 0.f; av[j][3] = 0.f;
            if (r0 + row < N_NODES) {
                uint2 u = __ldg(((const uint2*)Ain) + (size_t)(r0 + row) * KQ + kq);
                float2 f0 = __half22float2(*(const __half2*)&u.x);
                float2 f1 = __half22float2(*(const __half2*)&u.y);
                av[j][0] = f0.x; av[j][1] = f0.y; av[j][2] = f1.x; av[j][3] = f1.y;
            }
        }
        #pragma unroll
        for (int j = 0; j < NIT; j++) {
            int i = tid + j * 256;
            int row = i / KQ, kq = i - row * KQ;
            float4 b = B4[kq];
            float x0 = fmaxf(av[j][0] + b.x, 0.f);
            float x1 = fmaxf(av[j][1] + b.y, 0.f);
            float x2 = fmaxf(av[j][2] + b.z, 0.f);
            float x3 = fmaxf(av[j][3] + b.w, 0.f);
            __half2* pa = (__half2*)(sA + row * KP + kq * 4);
            pa[0] = __floats2half2_rn(x0, x1);
            pa[1] = __floats2half2_rn(x2, x3);
        }
    }
    __syncthreads();

    const int warp = tid >> 5;
    const int lane = tid & 31;
    const int g  = lane >> 2;
    const int t2 = (lane & 3) * 2;
    const int wrow = warp * 16;

    float acc[8][4];
    #pragma unroll
    for (int n = 0; n < 8; n++)
        #pragma unroll
        for (int c = 0; c < 4; c++) acc[n][c] = 0.f;

    #pragma unroll
    for (int kb = 0; kb < K / 16; kb++) {
        const int kO = kb * 16 + t2;
        unsigned a[4];
        {
            int rA = wrow + g;
            const unsigned* p0 = (const unsigned*)(sA + rA * KP + kO);
            const unsigned* p8 = (const unsigned*)(sA + (rA + 8) * KP + kO);
            a[0] = p0[0]; a[1] = p8[0]; a[2] = p0[4]; a[3] = p8[4];
        }
        #pragma unroll
        for (int n = 0; n < 8; n++) {
            int rB = n * 8 + g;
            const unsigned* qH = (const unsigned*)(sWhi + rB * KP + kO);
            const unsigned* qL = (const unsigned*)(sWlo + rB * KP + kO);
            unsigned bh0 = qH[0], bh1 = qH[4];
            unsigned bl0 = qL[0], bl1 = qL[4];
            mma_f16(acc[n], a, bh0, bh1);
            mma_f16(acc[n], a, bl0, bl1);
        }
    }

    __half2* C2 = (__half2*)C;
    int r  = r0 + wrow + g;
    int r8 = r + 8;
    float dv  = (r  < N_NODES) ? g_dinv[r]  : 0.f;
    float dv8 = (r8 < N_NODES) ? g_dinv[r8] : 0.f;
    #pragma unroll
    for (int n = 0; n < 8; n++) {
        if (r < N_NODES)
            C2[(size_t)r * 32 + n * 4 + (t2 >> 1)] =
                __floats2half2_rn(acc[n][0] * dv, acc[n][1] * dv);
        if (r8 < N_NODES)
            C2[(size_t)r8 * 32 + n * 4 + (t2 >> 1)] =
                __floats2half2_rn(acc[n][2] * dv8, acc[n][3] * dv8);
    }
}

// ---------------- CSR aggregation: 2 nodes per thread, interleaved gathers -----
// 8 threads per node slot; thread owns nodes (n, n+N/2) and features q*8..q*8+7.
__device__ __forceinline__ void acc_row(float* a, uint4 r) {
    const __half2* p = (const __half2*)&r;
    #pragma unroll
    for (int i = 0; i < 4; i++) {
        float2 f = __half22float2(p[i]);
        a[2 * i] += f.x; a[2 * i + 1] += f.y;
    }
}

__global__ void k_aggregate() {
    int idx = blockIdx.x * blockDim.x + threadIdx.x;   // over (N/2)*8
    if (idx >= N_HALF * 8) return;
    int nodeA = idx >> 3;
    int nodeB = nodeA + N_HALF;
    int q = idx & 7;
    const uint4* h4 = (const uint4*)g_hH;

    float aA0[8], aA1[8], aB0[8], aB1[8];
    #pragma unroll
    for (int i = 0; i < 8; i++) { aA0[i] = 0.f; aA1[i] = 0.f; aB0[i] = 0.f; aB1[i] = 0.f; }

    // self rows (independent)
    uint4 selfA = h4[(size_t)nodeA * 8 + q];
    uint4 selfB = h4[(size_t)nodeB * 8 + q];
    acc_row(aA0, selfA);
    acc_row(aB0, selfB);

    int eA = __ldg(&g_rowoff[nodeA]), eAe = __ldg(&g_rowoff[nodeA + 1]);
    int eB = __ldg(&g_rowoff[nodeB]), eBe = __ldg(&g_rowoff[nodeB + 1]);

    // interleaved phase: 2 edges from each node per iteration (4 gathers in flight)
    while (eA + 2 <= eAe && eB + 2 <= eBe) {
        int sa0 = __ldg(&g_csr[eA]);
        int sa1 = __ldg(&g_csr[eA + 1]);
        int sb0 = __ldg(&g_csr[eB]);
        int sb1 = __ldg(&g_csr[eB + 1]);
        uint4 ra0 = h4[(size_t)sa0 * 8 + q];
        uint4 ra1 = h4[(size_t)sa1 * 8 + q];
        uint4 rb0 = h4[(size_t)sb0 * 8 + q];
        uint4 rb1 = h4[(size_t)sb1 * 8 + q];
        acc_row(aA0, ra0);
        acc_row(aA1, ra1);
        acc_row(aB0, rb0);
        acc_row(aB1, rb1);
        eA += 2; eB += 2;
    }
    // drain node A (2-wide then single)
    for (; eA + 2 <= eAe; eA += 2) {
        int s0 = __ldg(&g_csr[eA]);
        int s1 = __ldg(&g_csr[eA + 1]);
        uint4 r0 = h4[(size_t)s0 * 8 + q];
        uint4 r1 = h4[(size_t)s1 * 8 + q];
        acc_row(aA0, r0);
        acc_row(aA1, r1);
    }
    if (eA < eAe) {
        int s0 = __ldg(&g_csr[eA]);
        acc_row(aA0, h4[(size_t)s0 * 8 + q]);
    }
    // drain node B
    for (; eB + 2 <= eBe; eB += 2) {
        int s0 = __ldg(&g_csr[eB]);
        int s1 = __ldg(&g_csr[eB + 1]);
        uint4 r0 = h4[(size_t)s0 * 8 + q];
        uint4 r1 = h4[(size_t)s1 * 8 + q];
        acc_row(aB0, r0);
        acc_row(aB1, r1);
    }
    if (eB < eBe) {
        int s0 = __ldg(&g_csr[eB]);
        acc_row(aB0, h4[(size_t)s0 * 8 + q]);
    }

    float dvA = g_dinv[nodeA];
    float dvB = g_dinv[nodeB];
    uint4 oA, oB;
    __half2* pA = (__half2*)&oA;
    __half2* pB = (__half2*)&oB;
    #pragma unroll
    for (int i = 0; i < 4; i++) {
        pA[i] = __floats2half2_rn((aA0[2 * i] + aA1[2 * i]) * dvA,
                                  (aA0[2 * i + 1] + aA1[2 * i + 1]) * dvA);
        pB[i] = __floats2half2_rn((aB0[2 * i] + aB1[2 * i]) * dvB,
                                  (aB0[2 * i + 1] + aB1[2 * i + 1]) * dvB);
    }
    ((uint4*)g_aggH)[(size_t)nodeA * 8 + q] = oA;
    ((uint4*)g_aggH)[(size_t)nodeB * 8 + q] = oB;
}

// ---------------- attention + pooling + final linear ---------------------------
__global__ void k_attn(const float* __restrict__ Wa, const float* __restrict__ v,
                       const float* __restrict__ Wl, const float* __restrict__ bl,
                       const float* __restrict__ b3,
                       float* __restrict__ out, float* __restrict__ lw) {
    __shared__ float sWaT[64 * 68];
    __shared__ float sWl[128 * 32];
    __shared__ float sV[64];
    __shared__ float sBl[32];
    __shared__ float sB3[64];
    __shared__ float sH[8][LEADS * 64];
    __shared__ float sScore[8][LEADS];
    __shared__ float sPool[8][128];

    int tid = threadIdx.x;
    for (int i = tid; i < 4096; i += 256) {
        int k = i >> 6, c = i & 63;
        sWaT[c * 68 + k] = Wa[i];
        sWl[i] = Wl[i];
    }
    if (tid < 64) { sV[tid] = v[tid]; sB3[tid] = b3[tid]; }
    if (tid < 32) sBl[tid] = bl[tid];
    __syncthreads();

    int w = tid >> 5, lane = tid & 31;
    int g = blockIdx.x * 8 + w;
    if (g >= NUM_GRAPHS) return;

    float* hs = sH[w];
    const uint4* hg = (const uint4*)(g_aggH + (size_t)g * (LEADS * 64));  // 96 uint4
    #pragma unroll
    for (int j = 0; j < 3; j++) {
        int id = lane + 32 * j;      // 0..95
        uint4 u = hg[id];
        int lead = id >> 3;
        int fb = (id & 7) * 8;
        const __half2* p = (const __half2*)&u;
        #pragma unroll
        for (int i = 0; i < 4; i++) {
            float2 f = __half22float2(p[i]);
            hs[lead * 64 + fb + 2 * i]     = fmaxf(f.x + sB3[fb + 2 * i], 0.f);
            hs[lead * 64 + fb + 2 * i + 1] = fmaxf(f.y + sB3[fb + 2 * i + 1], 0.f);
        }
    }
    __syncwarp();

    unsigned long long e0a[LEADS], e1a[LEADS];
    #pragma unroll
    for (int l = 0; l < LEADS; l++) { e0a[l] = 0ULL; e1a[l] = 0ULL; }
    const float* w0base = sWaT + lane * 68;
    const float* w1base = sWaT + (lane + 32) * 68;
    #pragma unroll 4
    for (int k4 = 0; k4 < 16; k4++) {
        ulonglong2 w0 = *(const ulonglong2*)(w0base + k4 * 4);
        ulonglong2 w1 = *(const ulonglong2*)(w1base + k4 * 4);
        #pragma unroll
        for (int l = 0; l < LEADS; l++) {
            ulonglong2 a = *(const ulonglong2*)(hs + l * 64 + k4 * 4);
            fma2(e0a[l], a.x, w0.x); fma2(e0a[l], a.y, w0.y);
            fma2(e1a[l], a.x, w1.x); fma2(e1a[l], a.y, w1.y);
        }
    }
    float v0 = sV[lane], v1 = sV[lane + 32];
    #pragma unroll
    for (int l = 0; l < LEADS; l++) {
        float s = tanhf(hsum2(e0a[l])) * v0 + tanhf(hsum2(e1a[l])) * v1;
        #pragma unroll
        for (int o = 16; o > 0; o >>= 1) s += __shfl_xor_sync(0xffffffff, s, o);
        if (lane == 0) sScore[w][l] = s;
    }
    __syncwarp();

    float sc[LEADS];
    #pragma unroll
    for (int l = 0; l < LEADS; l++) sc[l] = sScore[w][l];
    float m = sc[0];
    #pragma unroll
    for (int l = 1; l < LEADS; l++) m = fmaxf(m, sc[l]);
    float sum = 0.f;
    #pragma unroll
    for (int l = 0; l < LEADS; l++) { sc[l] = expf(sc[l] - m); sum += sc[l]; }
    float inv = 1.f / sum;
    #pragma unroll
    for (int l = 0; l < LEADS; l++) sc[l] *= inv;
    if (lane < LEADS) lw[(size_t)g * LEADS + lane] = sc[lane];

    #pragma unroll
    for (int half = 0; half < 2; half++) {
        int f = lane + 32 * half;
        float mx = -1e30f, sm = 0.f;
        #pragma unroll
        for (int l = 0; l < LEADS; l++) {
            float val = hs[l * 64 + f] * sc[l];
            mx = fmaxf(mx, val);
            sm += val;
        }
        sPool[w][f] = mx;
        sPool[w][64 + f] = sm * (1.f / 12.f);
    }
    __syncwarp();

    float acc = sBl[lane];
    #pragma unroll 16
    for (int f = 0; f < 128; f++) acc += sPool[w][f] * sWl[f * 32 + lane];
    out[(size_t)g * 32 + lane] = fmaxf(acc, 0.f);
}

// ---------------- launch --------------------------------------------------------
extern "C" void kernel_launch(void* const* d_in, const int* in_sizes, int n_in,
                              void* d_out, int out_size) {
    const float* x    = (const float*)d_in[0];
    const int*   ei   = (const int*)d_in[1];
    const int*   srcp = ei;
    const int*   dstp = ei + N_EDGES;
    const float* W1 = (const float*)d_in[3];
    const float* b1 = (const float*)d_in[4];
    const float* W2 = (const float*)d_in[5];
    const float* b2 = (const float*)d_in[6];
    const float* W3 = (const float*)d_in[7];
    const float* b3 = (const float*)d_in[8];
    const float* Wa = (const float*)d_in[9];
    const float* vv = (const float*)d_in[10];
    const float* Wl = (const float*)d_in[11];
    const float* bl = (const float*)d_in[12];

    float* out = (float*)d_out;                                  // [G,32]
    float* lw  = (float*)d_out + (size_t)NUM_GRAPHS * OUT_DIM;   // [G,12]

    __half* hp;  cudaGetSymbolAddress((void**)&hp,  g_hH);
    __half* ap;  cudaGetSymbolAddress((void**)&ap,  g_aggH);

    const int SM1 = (2 * 128 + 2 * 64) * (128 + 8) * 2;   // 104448 B
    const int SM2 = (128 + 2 * 64) * (64 + 8) * 2;        //  36864 B
    cudaFuncSetAttribute(k_gemm1,    cudaFuncAttributeMaxDynamicSharedMemorySize, SM1);
    cudaFuncSetAttribute(k_gemm_f16, cudaFuncAttributeMaxDynamicSharedMemorySize, SM2);

    const int T = 256;
    const int gN = (N_NODES + T - 1) / T;
    const int gE = (N_EDGES + T - 1) / T;
    const int GRID = (N_NODES + 127) / 128;
    const int AGG_GRID = (N_HALF * 8 + T - 1) / T;

    // launches 1-3
    k_deg_zero<<<gN, T>>>();
    k_deg_count<<<gE, T>>>(dstp);
    k_dinv<<<gN, T>>>();

    // launch 4 (ncu-profiled slot): tensor-core layer-1 GEMM
    k_gemm1<<<GRID, 256, SM1>>>(x, W1, hp);

    // CSR build
    k_scan1<<<SCAN_NB, 1024>>>();
    k_scan2<<<1, 1024>>>();
    k_scan3<<<(N_NODES + 1023) / 1024, 1024>>>();
    k_place<<<gE, T>>>(srcp, dstp);

    k_aggregate<<<AGG_GRID, T>>>();
    k_gemm_f16<<<GRID, 256, SM2>>>(ap, W2, b1, hp);
    k_aggregate<<<AGG_GRID, T>>>();
    k_gemm_f16<<<GRID, 256, SM2>>>(ap, W3, b2, hp);
    k_aggregate<<<AGG_GRID, T>>>();

    k_attn<<<(NUM_GRAPHS + 7) / 8, 256>>>(Wa, vv, Wl, bl, b3, out, lw);
}

// round 14
// speedup vs baseline: 1.3854x; 1.0354x over previous
#include <cuda_runtime.h>
#include <cuda_fp16.h>
#include <cuda_bf16.h>

#define N_NODES 600000
#define N_QUART 150000
#define N_EDGES 2400000
#define LEADS 12
#define NUM_GRAPHS 50000
#define F_IN 128
#define HDIM 64
#define OUT_DIM 32

#define SCAN_NB 586   // ceil(600000/1024)

// ---------------- packed fp32x2 FMA (used in attention) ------------------------
__device__ __forceinline__ void fma2(unsigned long long& d,
                                     unsigned long long a,
                                     unsigned long long b) {
    asm("fma.rn.f32x2 %0, %1, %2, %0;" : "+l"(d) : "l"(a), "l"(b));
}
__device__ __forceinline__ float hsum2(unsigned long long d) {
    float lo = __uint_as_float((unsigned int)(d & 0xffffffffULL));
    float hi = __uint_as_float((unsigned int)(d >> 32));
    return lo + hi;
}

// ---------------- mma m16n8k16, fp32 accumulate ---------------------------------
__device__ __forceinline__ void mma_f16(float* c, const unsigned* a,
                                        unsigned b0, unsigned b1) {
    asm volatile(
        "mma.sync.aligned.m16n8k16.row.col.f32.f16.f16.f32 "
        "{%0,%1,%2,%3}, {%4,%5,%6,%7}, {%8,%9}, {%0,%1,%2,%3};"
        : "+f"(c[0]), "+f"(c[1]), "+f"(c[2]), "+f"(c[3])
        : "r"(a[0]), "r"(a[1]), "r"(a[2]), "r"(a[3]), "r"(b0), "r"(b1));
}

// ---------------- scratch (device globals) ------------------------------------
__device__ __half g_hH  [(size_t)N_NODES * HDIM];  // GEMM output (gather source)
__device__ __half g_aggH[(size_t)N_NODES * HDIM];  // aggregated layer output
__device__ float  g_dinv[N_NODES];
__device__ int    g_deg[N_NODES];
__device__ int    g_rowoff[N_NODES + 1];
__device__ int    g_cursor[N_NODES];
__device__ int    g_csr[N_EDGES];
__device__ int    g_bsum[SCAN_NB];
__device__ int    g_boff[SCAN_NB];

// ---------------- degree / CSR build -------------------------------------------
__global__ void k_deg_zero() {
    int i = blockIdx.x * blockDim.x + threadIdx.x;
    if (i < N_NODES) g_deg[i] = 0;
}

__global__ void k_deg_count(const int* __restrict__ dst) {
    int e = blockIdx.x * blockDim.x + threadIdx.x;
    if (e < N_EDGES) atomicAdd(&g_deg[dst[e]], 1);
}

__global__ void k_dinv() {
    int i = blockIdx.x * blockDim.x + threadIdx.x;
    if (i < N_NODES) g_dinv[i] = rsqrtf((float)(g_deg[i] + 1));
}

__global__ void k_scan1() {
    __shared__ int sh[1024];
    int i = blockIdx.x * 1024 + threadIdx.x;
    int v = (i < N_NODES) ? g_deg[i] : 0;
    sh[threadIdx.x] = v;
    __syncthreads();
    #pragma unroll
    for (int off = 1; off < 1024; off <<= 1) {
        int t = 0;
        if (threadIdx.x >= off) t = sh[threadIdx.x - off];
        __syncthreads();
        if (threadIdx.x >= off) sh[threadIdx.x] += t;
        __syncthreads();
    }
    if (i < N_NODES) g_rowoff[i] = sh[threadIdx.x] - v;   // exclusive
    if (threadIdx.x == 1023) g_bsum[blockIdx.x] = sh[1023];
}

__global__ void k_scan2() {
    __shared__ int sh[1024];
    int v = (threadIdx.x < SCAN_NB) ? g_bsum[threadIdx.x] : 0;
    sh[threadIdx.x] = v;
    __syncthreads();
    #pragma unroll
    for (int off = 1; off < 1024; off <<= 1) {
        int t = 0;
        if (threadIdx.x >= off) t = sh[threadIdx.x - off];
        __syncthreads();
        if (threadIdx.x >= off) sh[threadIdx.x] += t;
        __syncthreads();
    }
    if (threadIdx.x < SCAN_NB) g_boff[threadIdx.x] = sh[threadIdx.x] - v;
}

__global__ void k_scan3() {
    int i = blockIdx.x * blockDim.x + threadIdx.x;
    if (i < N_NODES) {
        int ro = g_rowoff[i] + g_boff[i >> 10];
        g_rowoff[i] = ro;
        g_cursor[i] = ro;
    }
    if (i == 0) g_rowoff[N_NODES] = N_EDGES;
}

__global__ void k_place(const int* __restrict__ src, const int* __restrict__ dst) {
    int e = blockIdx.x * blockDim.x + threadIdx.x;
    if (e < N_EDGES) {
        int pos = atomicAdd(&g_cursor[dst[e]], 1);
        g_csr[pos] = src[e];
    }
}

// ---------------- layer-1 GEMM (fp32 input -> fp16 A, fp16 W hi/lo, 2 HMMA) ----
__global__ void k_gemm1(const float* __restrict__ Ain, const float* __restrict__ W,
                        __half* __restrict__ C) {
    constexpr int K = 128, BM = 128;
    constexpr int KP = K + 8;
    constexpr int KQ = K / 4;
    constexpr int NIT = BM * KQ / 256;   // 16
    extern __shared__ char smem_raw[];
    __half* sA   = (__half*)smem_raw;        // [BM][KP]
    __half* sWhi = sA + BM * KP;             // [64][KP] (transposed)
    __half* sWlo = sWhi + 64 * KP;           // [64][KP]

    const int tid = threadIdx.x;
    const int r0 = blockIdx.x * BM;

    for (int i = tid; i < K * 64; i += 256) {
        int k = i >> 6, c = i & 63;
        float w = W[i];
        __half hi = __float2half_rn(w);
        sWhi[c * KP + k] = hi;
        sWlo[c * KP + k] = __float2half_rn(w - __half2float(hi));
    }

    #pragma unroll
    for (int base = 0; base < NIT; base += 8) {
        float av[8][4];
        #pragma unroll
        for (int j = 0; j < 8; j++) {
            int i = tid + (base + j) * 256;
            int row = i / KQ, kq = i - row * KQ;
            av[j][0] = 0.f; av[j][1] = 0.f; av[j][2] = 0.f; av[j][3] = 0.f;
            if (r0 + row < N_NODES) {
                float4 a = __ldg(((const float4*)Ain) + (size_t)(r0 + row) * KQ + kq);
                av[j][0] = a.x; av[j][1] = a.y; av[j][2] = a.z; av[j][3] = a.w;
            }
        }
        #pragma unroll
        for (int j = 0; j < 8; j++) {
            int i = tid + (base + j) * 256;
            int row = i / KQ, kq = i - row * KQ;
            __half2* pa = (__half2*)(sA + row * KP + kq * 4);
            pa[0] = __floats2half2_rn(av[j][0], av[j][1]);
            pa[1] = __floats2half2_rn(av[j][2], av[j][3]);
        }
    }
    __syncthreads();

    const int warp = tid >> 5;
    const int lane = tid & 31;
    const int g  = lane >> 2;
    const int t2 = (lane & 3) * 2;
    const int wrow = warp * 16;

    float acc[8][4];
    #pragma unroll
    for (int n = 0; n < 8; n++)
        #pragma unroll
        for (int c = 0; c < 4; c++) acc[n][c] = 0.f;

    #pragma unroll
    for (int kb = 0; kb < K / 16; kb++) {
        const int kO = kb * 16 + t2;
        unsigned a[4];
        {
            int rA = wrow + g;
            const unsigned* p0 = (const unsigned*)(sA + rA * KP + kO);
            const unsigned* p8 = (const unsigned*)(sA + (rA + 8) * KP + kO);
            a[0] = p0[0]; a[1] = p8[0]; a[2] = p0[4]; a[3] = p8[4];
        }
        #pragma unroll
        for (int n = 0; n < 8; n++) {
            int rB = n * 8 + g;
            const unsigned* qH = (const unsigned*)(sWhi + rB * KP + kO);
            const unsigned* qL = (const unsigned*)(sWlo + rB * KP + kO);
            unsigned bh0 = qH[0], bh1 = qH[4];
            unsigned bl0 = qL[0], bl1 = qL[4];
            mma_f16(acc[n], a, bh0, bh1);
            mma_f16(acc[n], a, bl0, bl1);
        }
    }

    __half2* C2 = (__half2*)C;
    int r  = r0 + wrow + g;
    int r8 = r + 8;
    float dv  = (r  < N_NODES) ? g_dinv[r]  : 0.f;
    float dv8 = (r8 < N_NODES) ? g_dinv[r8] : 0.f;
    #pragma unroll
    for (int n = 0; n < 8; n++) {
        if (r < N_NODES)
            C2[(size_t)r * 32 + n * 4 + (t2 >> 1)] =
                __floats2half2_rn(acc[n][0] * dv, acc[n][1] * dv);
        if (r8 < N_NODES)
            C2[(size_t)r8 * 32 + n * 4 + (t2 >> 1)] =
                __floats2half2_rn(acc[n][2] * dv8, acc[n][3] * dv8);
    }
}

// ---------------- layers 2/3 GEMM (fp16 input): native fp16 MMA, W hi/lo -------
__global__ void k_gemm_f16(const __half* __restrict__ Ain, const float* __restrict__ W,
                           const float* __restrict__ bias, __half* __restrict__ C) {
    constexpr int K = 64, BM = 128;
    constexpr int KP = K + 8;
    constexpr int KQ = K / 4;
    constexpr int NIT = BM * KQ / 256;   // 8
    extern __shared__ char smem_raw[];
    __half* sA   = (__half*)smem_raw;        // [BM][KP]
    __half* sWhi = sA + BM * KP;             // [64][KP] (transposed)
    __half* sWlo = sWhi + 64 * KP;           // [64][KP]

    const int tid = threadIdx.x;
    const int r0 = blockIdx.x * BM;

    for (int i = tid; i < K * 64; i += 256) {
        int k = i >> 6, c = i & 63;
        float w = W[i];
        __half hi = __float2half_rn(w);
        sWhi[c * KP + k] = hi;
        sWlo[c * KP + k] = __float2half_rn(w - __half2float(hi));
    }

    const float4* B4 = (const float4*)bias;
    {
        float av[NIT][4];
        #pragma unroll
        for (int j = 0; j < NIT; j++) {
            int i = tid + j * 256;
            int row = i / KQ, kq = i - row * KQ;
            av[j][0] = 0.f; av[j][1] = 0.f; av[j][2] = 0.f; av[j][3] = 0.f;
            if (r0 + row < N_NODES) {
                uint2 u = __ldg(((const uint2*)Ain) + (size_t)(r0 + row) * KQ + kq);
                float2 f0 = __half22float2(*(const __half2*)&u.x);
                float2 f1 = __half22float2(*(const __half2*)&u.y);
                av[j][0] = f0.x; av[j][1] = f0.y; av[j][2] = f1.x; av[j][3] = f1.y;
            }
        }
        #pragma unroll
        for (int j = 0; j < NIT; j++) {
            int i = tid + j * 256;
            int row = i / KQ, kq = i - row * KQ;
            float4 b = B4[kq];
            float x0 = fmaxf(av[j][0] + b.x, 0.f);
            float x1 = fmaxf(av[j][1] + b.y, 0.f);
            float x2 = fmaxf(av[j][2] + b.z, 0.f);
            float x3 = fmaxf(av[j][3] + b.w, 0.f);
            __half2* pa = (__half2*)(sA + row * KP + kq * 4);
            pa[0] = __floats2half2_rn(x0, x1);
            pa[1] = __floats2half2_rn(x2, x3);
        }
    }
    __syncthreads();

    const int warp = tid >> 5;
    const int lane = tid & 31;
    const int g  = lane >> 2;
    const int t2 = (lane & 3) * 2;
    const int wrow = warp * 16;

    float acc[8][4];
    #pragma unroll
    for (int n = 0; n < 8; n++)
        #pragma unroll
        for (int c = 0; c < 4; c++) acc[n][c] = 0.f;

    #pragma unroll
    for (int kb = 0; kb < K / 16; kb++) {
        const int kO = kb * 16 + t2;
        unsigned a[4];
        {
            int rA = wrow + g;
            const unsigned* p0 = (const unsigned*)(sA + rA * KP + kO);
            const unsigned* p8 = (const unsigned*)(sA + (rA + 8) * KP + kO);
            a[0] = p0[0]; a[1] = p8[0]; a[2] = p0[4]; a[3] = p8[4];
        }
        #pragma unroll
        for (int n = 0; n < 8; n++) {
            int rB = n * 8 + g;
            const unsigned* qH = (const unsigned*)(sWhi + rB * KP + kO);
            const unsigned* qL = (const unsigned*)(sWlo + rB * KP + kO);
            unsigned bh0 = qH[0], bh1 = qH[4];
            unsigned bl0 = qL[0], bl1 = qL[4];
            mma_f16(acc[n], a, bh0, bh1);
            mma_f16(acc[n], a, bl0, bl1);
        }
    }

    __half2* C2 = (__half2*)C;
    int r  = r0 + wrow + g;
    int r8 = r + 8;
    float dv  = (r  < N_NODES) ? g_dinv[r]  : 0.f;
    float dv8 = (r8 < N_NODES) ? g_dinv[r8] : 0.f;
    #pragma unroll
    for (int n = 0; n < 8; n++) {
        if (r < N_NODES)
            C2[(size_t)r * 32 + n * 4 + (t2 >> 1)] =
                __floats2half2_rn(acc[n][0] * dv, acc[n][1] * dv);
        if (r8 < N_NODES)
            C2[(size_t)r8 * 32 + n * 4 + (t2 >> 1)] =
                __floats2half2_rn(acc[n][2] * dv8, acc[n][3] * dv8);
    }
}

// ---------------- CSR aggregation: 4 nodes per thread, predicated gathers ------
// 8 threads per node slot; thread owns nodes n + k*N/4 and features q*8..q*8+7.
// Each loop iteration issues up to 4 independent gathers (one per live node).
__device__ __forceinline__ void acc_row(float* a, uint4 r) {
    const __half2* p = (const __half2*)&r;
    #pragma unroll
    for (int i = 0; i < 4; i++) {
        float2 f = __half22float2(p[i]);
        a[2 * i] += f.x; a[2 * i + 1] += f.y;
    }
}

__global__ void k_aggregate() {
    int idx = blockIdx.x * blockDim.x + threadIdx.x;   // over (N/4)*8
    if (idx >= N_QUART * 8) return;
    int n0 = idx >> 3;
    int q = idx & 7;
    const uint4* h4 = (const uint4*)g_hH;

    int node[4], e[4], ee[4];
    float acc[4][8];
    #pragma unroll
    for (int k = 0; k < 4; k++) {
        node[k] = n0 + k * N_QUART;
        #pragma unroll
        for (int i = 0; i < 8; i++) acc[k][i] = 0.f;
    }
    // self rows (4 independent loads)
    {
        uint4 s0 = h4[(size_t)node[0] * 8 + q];
        uint4 s1 = h4[(size_t)node[1] * 8 + q];
        uint4 s2 = h4[(size_t)node[2] * 8 + q];
        uint4 s3 = h4[(size_t)node[3] * 8 + q];
        acc_row(acc[0], s0);
        acc_row(acc[1], s1);
        acc_row(acc[2], s2);
        acc_row(acc[3], s3);
    }
    #pragma unroll
    for (int k = 0; k < 4; k++) {
        e[k]  = __ldg(&g_rowoff[node[k]]);
        ee[k] = __ldg(&g_rowoff[node[k] + 1]);
    }

    while ((e[0] < ee[0]) | (e[1] < ee[1]) | (e[2] < ee[2]) | (e[3] < ee[3])) {
        int s[4];
        #pragma unroll
        for (int k = 0; k < 4; k++)
            s[k] = (e[k] < ee[k]) ? __ldg(&g_csr[e[k]]) : -1;
        uint4 r[4];
        #pragma unroll
        for (int k = 0; k < 4; k++)
            if (s[k] >= 0) r[k] = h4[(size_t)s[k] * 8 + q];
        #pragma unroll
        for (int k = 0; k < 4; k++)
            if (s[k] >= 0) { acc_row(acc[k], r[k]); e[k]++; }
    }

    #pragma unroll
    for (int k = 0; k < 4; k++) {
        float dv = g_dinv[node[k]];
        uint4 o;
        __half2* po = (__half2*)&o;
        #pragma unroll
        for (int i = 0; i < 4; i++)
            po[i] = __floats2half2_rn(acc[k][2 * i] * dv, acc[k][2 * i + 1] * dv);
        ((uint4*)g_aggH)[(size_t)node[k] * 8 + q] = o;
    }
}

// ---------------- attention + pooling + final linear ---------------------------
__global__ void k_attn(const float* __restrict__ Wa, const float* __restrict__ v,
                       const float* __restrict__ Wl, const float* __restrict__ bl,
                       const float* __restrict__ b3,
                       float* __restrict__ out, float* __restrict__ lw) {
    __shared__ float sWaT[64 * 68];
    __shared__ float sWl[128 * 32];
    __shared__ float sV[64];
    __shared__ float sBl[32];
    __shared__ float sB3[64];
    __shared__ float sH[8][LEADS * 64];
    __shared__ float sScore[8][LEADS];
    __shared__ float sPool[8][128];

    int tid = threadIdx.x;
    for (int i = tid; i < 4096; i += 256) {
        int k = i >> 6, c = i & 63;
        sWaT[c * 68 + k] = Wa[i];
        sWl[i] = Wl[i];
    }
    if (tid < 64) { sV[tid] = v[tid]; sB3[tid] = b3[tid]; }
    if (tid < 32) sBl[tid] = bl[tid];
    __syncthreads();

    int w = tid >> 5, lane = tid & 31;
    int g = blockIdx.x * 8 + w;
    if (g >= NUM_GRAPHS) return;

    float* hs = sH[w];
    const uint4* hg = (const uint4*)(g_aggH + (size_t)g * (LEADS * 64));  // 96 uint4
    #pragma unroll
    for (int j = 0; j < 3; j++) {
        int id = lane + 32 * j;      // 0..95
        uint4 u = hg[id];
        int lead = id >> 3;
        int fb = (id & 7) * 8;
        const __half2* p = (const __half2*)&u;
        #pragma unroll
        for (int i = 0; i < 4; i++) {
            float2 f = __half22float2(p[i]);
            hs[lead * 64 + fb + 2 * i]     = fmaxf(f.x + sB3[fb + 2 * i], 0.f);
            hs[lead * 64 + fb + 2 * i + 1] = fmaxf(f.y + sB3[fb + 2 * i + 1], 0.f);
        }
    }
    __syncwarp();

    unsigned long long e0a[LEADS], e1a[LEADS];
    #pragma unroll
    for (int l = 0; l < LEADS; l++) { e0a[l] = 0ULL; e1a[l] = 0ULL; }
    const float* w0base = sWaT + lane * 68;
    const float* w1base = sWaT + (lane + 32) * 68;
    #pragma unroll 4
    for (int k4 = 0; k4 < 16; k4++) {
        ulonglong2 w0 = *(const ulonglong2*)(w0base + k4 * 4);
        ulonglong2 w1 = *(const ulonglong2*)(w1base + k4 * 4);
        #pragma unroll
        for (int l = 0; l < LEADS; l++) {
            ulonglong2 a = *(const ulonglong2*)(hs + l * 64 + k4 * 4);
            fma2(e0a[l], a.x, w0.x); fma2(e0a[l], a.y, w0.y);
            fma2(e1a[l], a.x, w1.x); fma2(e1a[l], a.y, w1.y);
        }
    }
    float v0 = sV[lane], v1 = sV[lane + 32];
    #pragma unroll
    for (int l = 0; l < LEADS; l++) {
        float s = tanhf(hsum2(e0a[l])) * v0 + tanhf(hsum2(e1a[l])) * v1;
        #pragma unroll
        for (int o = 16; o > 0; o >>= 1) s += __shfl_xor_sync(0xffffffff, s, o);
        if (lane == 0) sScore[w][l] = s;
    }
    __syncwarp();

    float sc[LEADS];
    #pragma unroll
    for (int l = 0; l < LEADS; l++) sc[l] = sScore[w][l];
    float m = sc[0];
    #pragma unroll
    for (int l = 1; l < LEADS; l++) m = fmaxf(m, sc[l]);
    float sum = 0.f;
    #pragma unroll
    for (int l = 0; l < LEADS; l++) { sc[l] = expf(sc[l] - m); sum += sc[l]; }
    float inv = 1.f / sum;
    #pragma unroll
    for (int l = 0; l < LEADS; l++) sc[l] *= inv;
    if (lane < LEADS) lw[(size_t)g * LEADS + lane] = sc[lane];

    #pragma unroll
    for (int half = 0; half < 2; half++) {
        int f = lane + 32 * half;
        float mx = -1e30f, sm = 0.f;
        #pragma unroll
        for (int l = 0; l < LEADS; l++) {
            float val = hs[l * 64 + f] * sc[l];
            mx = fmaxf(mx, val);
            sm += val;
        }
        sPool[w][f] = mx;
        sPool[w][64 + f] = sm * (1.f / 12.f);
    }
    __syncwarp();

    float acc = sBl[lane];
    #pragma unroll 16
    for (int f = 0; f < 128; f++) acc += sPool[w][f] * sWl[f * 32 + lane];
    out[(size_t)g * 32 + lane] = fmaxf(acc, 0.f);
}

// ---------------- launch --------------------------------------------------------
extern "C" void kernel_launch(void* const* d_in, const int* in_sizes, int n_in,
                              void* d_out, int out_size) {
    const float* x    = (const float*)d_in[0];
    const int*   ei   = (const int*)d_in[1];
    const int*   srcp = ei;
    const int*   dstp = ei + N_EDGES;
    const float* W1 = (const float*)d_in[3];
    const float* b1 = (const float*)d_in[4];
    const float* W2 = (const float*)d_in[5];
    const float* b2 = (const float*)d_in[6];
    const float* W3 = (const float*)d_in[7];
    const float* b3 = (const float*)d_in[8];
    const float* Wa = (const float*)d_in[9];
    const float* vv = (const float*)d_in[10];
    const float* Wl = (const float*)d_in[11];
    const float* bl = (const float*)d_in[12];

    float* out = (float*)d_out;                                  // [G,32]
    float* lw  = (float*)d_out + (size_t)NUM_GRAPHS * OUT_DIM;   // [G,12]

    __half* hp;  cudaGetSymbolAddress((void**)&hp,  g_hH);
    __half* ap;  cudaGetSymbolAddress((void**)&ap,  g_aggH);

    const int SM1 = (128 + 2 * 64) * (128 + 8) * 2;   // 69632 B
    const int SM2 = (128 + 2 * 64) * (64 + 8) * 2;    // 36864 B
    cudaFuncSetAttribute(k_gemm1,    cudaFuncAttributeMaxDynamicSharedMemorySize, SM1);
    cudaFuncSetAttribute(k_gemm_f16, cudaFuncAttributeMaxDynamicSharedMemorySize, SM2);

    const int T = 256;
    const int gN = (N_NODES + T - 1) / T;
    const int gE = (N_EDGES + T - 1) / T;
    const int GRID = (N_NODES + 127) / 128;
    const int AGG_GRID = (N_QUART * 8 + T - 1) / T;

    // launches 1-3
    k_deg_zero<<<gN, T>>>();
    k_deg_count<<<gE, T>>>(dstp);
    k_dinv<<<gN, T>>>();

    // launch 4 (ncu-profiled slot): layer-1 GEMM
    k_gemm1<<<GRID, 256, SM1>>>(x, W1, hp);

    // CSR build
    k_scan1<<<SCAN_NB, 1024>>>();
    k_scan2<<<1, 1024>>>();
    k_scan3<<<(N_NODES + 1023) / 1024, 1024>>>();
    k_place<<<gE, T>>>(srcp, dstp);

    k_aggregate<<<AGG_GRID, T>>>();
    k_gemm_f16<<<GRID, 256, SM2>>>(ap, W2, b1, hp);
    k_aggregate<<<AGG_GRID, T>>>();
    k_gemm_f16<<<GRID, 256, SM2>>>(ap, W3, b2, hp);
    k_aggregate<<<AGG_GRID, T>>>();

    k_attn<<<(NUM_GRAPHS + 7) / 8, 256>>>(Wa, vv, Wl, bl, b3, out, lw);
}

// round 15
// speedup vs baseline: 1.4662x; 1.0584x over previous
#include <cuda_runtime.h>
#include <cuda_fp16.h>
#include <cuda_bf16.h>

#define N_NODES 600000
#define N_QUART 150000
#define N_EDGES 2400000
#define LEADS 12
#define NUM_GRAPHS 50000
#define F_IN 128
#define HDIM 64
#define OUT_DIM 32

#define SCAN_NB 586   // ceil(600000/1024)

// ---------------- packed fp32x2 FMA (used in attention) ------------------------
__device__ __forceinline__ void fma2(unsigned long long& d,
                                     unsigned long long a,
                                     unsigned long long b) {
    asm("fma.rn.f32x2 %0, %1, %2, %0;" : "+l"(d) : "l"(a), "l"(b));
}
__device__ __forceinline__ float hsum2(unsigned long long d) {
    float lo = __uint_as_float((unsigned int)(d & 0xffffffffULL));
    float hi = __uint_as_float((unsigned int)(d >> 32));
    return lo + hi;
}

// ---------------- mma m16n8k16, fp32 accumulate ---------------------------------
__device__ __forceinline__ void mma_f16(float* c, const unsigned* a,
                                        unsigned b0, unsigned b1) {
    asm volatile(
        "mma.sync.aligned.m16n8k16.row.col.f32.f16.f16.f32 "
        "{%0,%1,%2,%3}, {%4,%5,%6,%7}, {%8,%9}, {%0,%1,%2,%3};"
        : "+f"(c[0]), "+f"(c[1]), "+f"(c[2]), "+f"(c[3])
        : "r"(a[0]), "r"(a[1]), "r"(a[2]), "r"(a[3]), "r"(b0), "r"(b1));
}

// ---------------- scratch (device globals) ------------------------------------
__device__ __half g_hH  [(size_t)N_NODES * HDIM];  // GEMM output (gather source)
__device__ __half g_aggH[(size_t)N_NODES * HDIM];  // aggregated layer output
__device__ float  g_dinv[N_NODES];
__device__ int    g_deg[N_NODES];
__device__ int    g_rowoff[N_NODES + 1];
__device__ int    g_cursor[N_NODES];
__device__ int    g_csr[N_EDGES];
__device__ int    g_bsum[SCAN_NB];
__device__ int    g_boff[SCAN_NB];

// ---------------- degree / CSR build -------------------------------------------
__global__ void k_deg_zero() {
    int i = blockIdx.x * blockDim.x + threadIdx.x;
    if (i < N_NODES) g_deg[i] = 0;
}

__global__ void k_deg_count(const int* __restrict__ dst) {
    int e = blockIdx.x * blockDim.x + threadIdx.x;
    if (e < N_EDGES) atomicAdd(&g_deg[dst[e]], 1);
}

__global__ void k_dinv() {
    int i = blockIdx.x * blockDim.x + threadIdx.x;
    if (i < N_NODES) g_dinv[i] = rsqrtf((float)(g_deg[i] + 1));
}

__global__ void k_scan1() {
    __shared__ int sh[1024];
    int i = blockIdx.x * 1024 + threadIdx.x;
    int v = (i < N_NODES) ? g_deg[i] : 0;
    sh[threadIdx.x] = v;
    __syncthreads();
    #pragma unroll
    for (int off = 1; off < 1024; off <<= 1) {
        int t = 0;
        if (threadIdx.x >= off) t = sh[threadIdx.x - off];
        __syncthreads();
        if (threadIdx.x >= off) sh[threadIdx.x] += t;
        __syncthreads();
    }
    if (i < N_NODES) g_rowoff[i] = sh[threadIdx.x] - v;   // exclusive
    if (threadIdx.x == 1023) g_bsum[blockIdx.x] = sh[1023];
}

__global__ void k_scan2() {
    __shared__ int sh[1024];
    int v = (threadIdx.x < SCAN_NB) ? g_bsum[threadIdx.x] : 0;
    sh[threadIdx.x] = v;
    __syncthreads();
    #pragma unroll
    for (int off = 1; off < 1024; off <<= 1) {
        int t = 0;
        if (threadIdx.x >= off) t = sh[threadIdx.x - off];
        __syncthreads();
        if (threadIdx.x >= off) sh[threadIdx.x] += t;
        __syncthreads();
    }
    if (threadIdx.x < SCAN_NB) g_boff[threadIdx.x] = sh[threadIdx.x] - v;
}

__global__ void k_scan3() {
    int i = blockIdx.x * blockDim.x + threadIdx.x;
    if (i < N_NODES) {
        int ro = g_rowoff[i] + g_boff[i >> 10];
        g_rowoff[i] = ro;
        g_cursor[i] = ro;
    }
    if (i == 0) g_rowoff[N_NODES] = N_EDGES;
}

__global__ void k_place(const int* __restrict__ src, const int* __restrict__ dst) {
    int e = blockIdx.x * blockDim.x + threadIdx.x;
    if (e < N_EDGES) {
        int pos = atomicAdd(&g_cursor[dst[e]], 1);
        g_csr[pos] = src[e];
    }
}

// ---------------- layer-1 GEMM (fp32 input -> fp16 A, fp16 W hi/lo, 2 HMMA) ----
__global__ void k_gemm1(const float* __restrict__ Ain, const float* __restrict__ W,
                        __half* __restrict__ C) {
    constexpr int K = 128, BM = 128;
    constexpr int KP = K + 8;
    constexpr int KQ = K / 4;
    constexpr int NIT = BM * KQ / 256;   // 16
    extern __shared__ char smem_raw[];
    __half* sA   = (__half*)smem_raw;        // [BM][KP]
    __half* sWhi = sA + BM * KP;             // [64][KP] (transposed)
    __half* sWlo = sWhi + 64 * KP;           // [64][KP]

    const int tid = threadIdx.x;
    const int r0 = blockIdx.x * BM;

    for (int i = tid; i < K * 64; i += 256) {
        int k = i >> 6, c = i & 63;
        float w = W[i];
        __half hi = __float2half_rn(w);
        sWhi[c * KP + k] = hi;
        sWlo[c * KP + k] = __float2half_rn(w - __half2float(hi));
    }

    #pragma unroll
    for (int base = 0; base < NIT; base += 8) {
        float av[8][4];
        #pragma unroll
        for (int j = 0; j < 8; j++) {
            int i = tid + (base + j) * 256;
            int row = i / KQ, kq = i - row * KQ;
            av[j][0] = 0.f; av[j][1] = 0.f; av[j][2] = 0.f; av[j][3] = 0.f;
            if (r0 + row < N_NODES) {
                float4 a = __ldg(((const float4*)Ain) + (size_t)(r0 + row) * KQ + kq);
                av[j][0] = a.x; av[j][1] = a.y; av[j][2] = a.z; av[j][3] = a.w;
            }
        }
        #pragma unroll
        for (int j = 0; j < 8; j++) {
            int i = tid + (base + j) * 256;
            int row = i / KQ, kq = i - row * KQ;
            __half2* pa = (__half2*)(sA + row * KP + kq * 4);
            pa[0] = __floats2half2_rn(av[j][0], av[j][1]);
            pa[1] = __floats2half2_rn(av[j][2], av[j][3]);
        }
    }
    __syncthreads();

    const int warp = tid >> 5;
    const int lane = tid & 31;
    const int g  = lane >> 2;
    const int t2 = (lane & 3) * 2;
    const int wrow = warp * 16;

    float acc[8][4];
    #pragma unroll
    for (int n = 0; n < 8; n++)
        #pragma unroll
        for (int c = 0; c < 4; c++) acc[n][c] = 0.f;

    #pragma unroll
    for (int kb = 0; kb < K / 16; kb++) {
        const int kO = kb * 16 + t2;
        unsigned a[4];
        {
            int rA = wrow + g;
            const unsigned* p0 = (const unsigned*)(sA + rA * KP + kO);
            const unsigned* p8 = (const unsigned*)(sA + (rA + 8) * KP + kO);
            a[0] = p0[0]; a[1] = p8[0]; a[2] = p0[4]; a[3] = p8[4];
        }
        #pragma unroll
        for (int n = 0; n < 8; n++) {
            int rB = n * 8 + g;
            const unsigned* qH = (const unsigned*)(sWhi + rB * KP + kO);
            const unsigned* qL = (const unsigned*)(sWlo + rB * KP + kO);
            unsigned bh0 = qH[0], bh1 = qH[4];
            unsigned bl0 = qL[0], bl1 = qL[4];
            mma_f16(acc[n], a, bh0, bh1);
            mma_f16(acc[n], a, bl0, bl1);
        }
    }

    __half2* C2 = (__half2*)C;
    int r  = r0 + wrow + g;
    int r8 = r + 8;
    float dv  = (r  < N_NODES) ? g_dinv[r]  : 0.f;
    float dv8 = (r8 < N_NODES) ? g_dinv[r8] : 0.f;
    #pragma unroll
    for (int n = 0; n < 8; n++) {
        if (r < N_NODES)
            C2[(size_t)r * 32 + n * 4 + (t2 >> 1)] =
                __floats2half2_rn(acc[n][0] * dv, acc[n][1] * dv);
        if (r8 < N_NODES)
            C2[(size_t)r8 * 32 + n * 4 + (t2 >> 1)] =
                __floats2half2_rn(acc[n][2] * dv8, acc[n][3] * dv8);
    }
}

// ---------------- layers 2/3 GEMM (fp16 input): native fp16 MMA, W hi/lo -------
__global__ void k_gemm_f16(const __half* __restrict__ Ain, const float* __restrict__ W,
                           const float* __restrict__ bias, __half* __restrict__ C) {
    constexpr int K = 64, BM = 128;
    constexpr int KP = K + 8;
    constexpr int KQ = K / 4;
    constexpr int NIT = BM * KQ / 256;   // 8
    extern __shared__ char smem_raw[];
    __half* sA   = (__half*)smem_raw;        // [BM][KP]
    __half* sWhi = sA + BM * KP;             // [64][KP] (transposed)
    __half* sWlo = sWhi + 64 * KP;           // [64][KP]

    const int tid = threadIdx.x;
    const int r0 = blockIdx.x * BM;

    for (int i = tid; i < K * 64; i += 256) {
        int k = i >> 6, c = i & 63;
        float w = W[i];
        __half hi = __float2half_rn(w);
        sWhi[c * KP + k] = hi;
        sWlo[c * KP + k] = __float2half_rn(w - __half2float(hi));
    }

    const float4* B4 = (const float4*)bias;
    {
        float av[NIT][4];
        #pragma unroll
        for (int j = 0; j < NIT; j++) {
            int i = tid + j * 256;
            int row = i / KQ, kq = i - row * KQ;
            av[j][0] = 0.f; av[j][1] = 0.f; av[j][2] = 0.f; av[j][3] = 0.f;
            if (r0 + row < N_NODES) {
                uint2 u = __ldg(((const uint2*)Ain) + (size_t)(r0 + row) * KQ + kq);
                float2 f0 = __half22float2(*(const __half2*)&u.x);
                float2 f1 = __half22float2(*(const __half2*)&u.y);
                av[j][0] = f0.x; av[j][1] = f0.y; av[j][2] = f1.x; av[j][3] = f1.y;
            }
        }
        #pragma unroll
        for (int j = 0; j < NIT; j++) {
            int i = tid + j * 256;
            int row = i / KQ, kq = i - row * KQ;
            float4 b = B4[kq];
            float x0 = fmaxf(av[j][0] + b.x, 0.f);
            float x1 = fmaxf(av[j][1] + b.y, 0.f);
            float x2 = fmaxf(av[j][2] + b.z, 0.f);
            float x3 = fmaxf(av[j][3] + b.w, 0.f);
            __half2* pa = (__half2*)(sA + row * KP + kq * 4);
            pa[0] = __floats2half2_rn(x0, x1);
            pa[1] = __floats2half2_rn(x2, x3);
        }
    }
    __syncthreads();

    const int warp = tid >> 5;
    const int lane = tid & 31;
    const int g  = lane >> 2;
    const int t2 = (lane & 3) * 2;
    const int wrow = warp * 16;

    float acc[8][4];
    #pragma unroll
    for (int n = 0; n < 8; n++)
        #pragma unroll
        for (int c = 0; c < 4; c++) acc[n][c] = 0.f;

    #pragma unroll
    for (int kb = 0; kb < K / 16; kb++) {
        const int kO = kb * 16 + t2;
        unsigned a[4];
        {
            int rA = wrow + g;
            const unsigned* p0 = (const unsigned*)(sA + rA * KP + kO);
            const unsigned* p8 = (const unsigned*)(sA + (rA + 8) * KP + kO);
            a[0] = p0[0]; a[1] = p8[0]; a[2] = p0[4]; a[3] = p8[4];
        }
        #pragma unroll
        for (int n = 0; n < 8; n++) {
            int rB = n * 8 + g;
            const unsigned* qH = (const unsigned*)(sWhi + rB * KP + kO);
            const unsigned* qL = (const unsigned*)(sWlo + rB * KP + kO);
            unsigned bh0 = qH[0], bh1 = qH[4];
            unsigned bl0 = qL[0], bl1 = qL[4];
            mma_f16(acc[n], a, bh0, bh1);
            mma_f16(acc[n], a, bl0, bl1);
        }
    }

    __half2* C2 = (__half2*)C;
    int r  = r0 + wrow + g;
    int r8 = r + 8;
    float dv  = (r  < N_NODES) ? g_dinv[r]  : 0.f;
    float dv8 = (r8 < N_NODES) ? g_dinv[r8] : 0.f;
    #pragma unroll
    for (int n = 0; n < 8; n++) {
        if (r < N_NODES)
            C2[(size_t)r * 32 + n * 4 + (t2 >> 1)] =
                __floats2half2_rn(acc[n][0] * dv, acc[n][1] * dv);
        if (r8 < N_NODES)
            C2[(size_t)r8 * 32 + n * 4 + (t2 >> 1)] =
                __floats2half2_rn(acc[n][2] * dv8, acc[n][3] * dv8);
    }
}

// ---------------- CSR aggregation: 4 nodes/thread + pipelined index loads ------
// 8 threads per node slot; thread owns nodes n + k*N/4 and features q*8..q*8+7.
// Next iteration's CSR indices are prefetched while current gathers are in flight.
__device__ __forceinline__ void acc_row(float* a, uint4 r) {
    const __half2* p = (const __half2*)&r;
    #pragma unroll
    for (int i = 0; i < 4; i++) {
        float2 f = __half22float2(p[i]);
        a[2 * i] += f.x; a[2 * i + 1] += f.y;
    }
}

__global__ void k_aggregate() {
    int idx = blockIdx.x * blockDim.x + threadIdx.x;   // over (N/4)*8
    if (idx >= N_QUART * 8) return;
    int n0 = idx >> 3;
    int q = idx & 7;
    const uint4* h4 = (const uint4*)g_hH;

    int node[4], e[4], ee[4];
    float acc[4][8];
    #pragma unroll
    for (int k = 0; k < 4; k++) {
        node[k] = n0 + k * N_QUART;
        #pragma unroll
        for (int i = 0; i < 8; i++) acc[k][i] = 0.f;
    }
    // self rows (4 independent loads)
    {
        uint4 s0 = h4[(size_t)node[0] * 8 + q];
        uint4 s1 = h4[(size_t)node[1] * 8 + q];
        uint4 s2 = h4[(size_t)node[2] * 8 + q];
        uint4 s3 = h4[(size_t)node[3] * 8 + q];
        acc_row(acc[0], s0);
        acc_row(acc[1], s1);
        acc_row(acc[2], s2);
        acc_row(acc[3], s3);
    }
    #pragma unroll
    for (int k = 0; k < 4; k++) {
        e[k]  = __ldg(&g_rowoff[node[k]]);
        ee[k] = __ldg(&g_rowoff[node[k] + 1]);
    }

    // prologue: load first index for each live node
    int s[4];
    #pragma unroll
    for (int k = 0; k < 4; k++)
        s[k] = (e[k] < ee[k]) ? __ldg(&g_csr[e[k]]) : -1;

    while ((s[0] >= 0) | (s[1] >= 0) | (s[2] >= 0) | (s[3] >= 0)) {
        // issue row gathers for current indices
        uint4 r[4];
        #pragma unroll
        for (int k = 0; k < 4; k++)
            if (s[k] >= 0) r[k] = h4[(size_t)s[k] * 8 + q];
        // prefetch next indices (overlaps with gather latency)
        int sn[4];
        #pragma unroll
        for (int k = 0; k < 4; k++) {
            int en = e[k] + 1;
            sn[k] = (s[k] >= 0 && en < ee[k]) ? __ldg(&g_csr[en]) : -1;
        }
        // accumulate + advance
        #pragma unroll
        for (int k = 0; k < 4; k++)
            if (s[k] >= 0) { acc_row(acc[k], r[k]); e[k]++; }
        #pragma unroll
        for (int k = 0; k < 4; k++) s[k] = sn[k];
    }

    #pragma unroll
    for (int k = 0; k < 4; k++) {
        float dv = g_dinv[node[k]];
        uint4 o;
        __half2* po = (__half2*)&o;
        #pragma unroll
        for (int i = 0; i < 4; i++)
            po[i] = __floats2half2_rn(acc[k][2 * i] * dv, acc[k][2 * i + 1] * dv);
        ((uint4*)g_aggH)[(size_t)node[k] * 8 + q] = o;
    }
}

// ---------------- attention + pooling + final linear ---------------------------
__global__ void k_attn(const float* __restrict__ Wa, const float* __restrict__ v,
                       const float* __restrict__ Wl, const float* __restrict__ bl,
                       const float* __restrict__ b3,
                       float* __restrict__ out, float* __restrict__ lw) {
    __shared__ float sWaT[64 * 68];
    __shared__ float sWl[128 * 32];
    __shared__ float sV[64];
    __shared__ float sBl[32];
    __shared__ float sB3[64];
    __shared__ float sH[8][LEADS * 64];
    __shared__ float sScore[8][LEADS];
    __shared__ float sPool[8][128];

    int tid = threadIdx.x;
    for (int i = tid; i < 4096; i += 256) {
        int k = i >> 6, c = i & 63;
        sWaT[c * 68 + k] = Wa[i];
        sWl[i] = Wl[i];
    }
    if (tid < 64) { sV[tid] = v[tid]; sB3[tid] = b3[tid]; }
    if (tid < 32) sBl[tid] = bl[tid];
    __syncthreads();

    int w = tid >> 5, lane = tid & 31;
    int g = blockIdx.x * 8 + w;
    if (g >= NUM_GRAPHS) return;

    float* hs = sH[w];
    const uint4* hg = (const uint4*)(g_aggH + (size_t)g * (LEADS * 64));  // 96 uint4
    #pragma unroll
    for (int j = 0; j < 3; j++) {
        int id = lane + 32 * j;      // 0..95
        uint4 u = hg[id];
        int lead = id >> 3;
        int fb = (id & 7) * 8;
        const __half2* p = (const __half2*)&u;
        #pragma unroll
        for (int i = 0; i < 4; i++) {
            float2 f = __half22float2(p[i]);
            hs[lead * 64 + fb + 2 * i]     = fmaxf(f.x + sB3[fb + 2 * i], 0.f);
            hs[lead * 64 + fb + 2 * i + 1] = fmaxf(f.y + sB3[fb + 2 * i + 1], 0.f);
        }
    }
    __syncwarp();

    unsigned long long e0a[LEADS], e1a[LEADS];
    #pragma unroll
    for (int l = 0; l < LEADS; l++) { e0a[l] = 0ULL; e1a[l] = 0ULL; }
    const float* w0base = sWaT + lane * 68;
    const float* w1base = sWaT + (lane + 32) * 68;
    #pragma unroll 4
    for (int k4 = 0; k4 < 16; k4++) {
        ulonglong2 w0 = *(const ulonglong2*)(w0base + k4 * 4);
        ulonglong2 w1 = *(const ulonglong2*)(w1base + k4 * 4);
        #pragma unroll
        for (int l = 0; l < LEADS; l++) {
            ulonglong2 a = *(const ulonglong2*)(hs + l * 64 + k4 * 4);
            fma2(e0a[l], a.x, w0.x); fma2(e0a[l], a.y, w0.y);
            fma2(e1a[l], a.x, w1.x); fma2(e1a[l], a.y, w1.y);
        }
    }
    float v0 = sV[lane], v1 = sV[lane + 32];
    #pragma unroll
    for (int l = 0; l < LEADS; l++) {
        float s = tanhf(hsum2(e0a[l])) * v0 + tanhf(hsum2(e1a[l])) * v1;
        #pragma unroll
        for (int o = 16; o > 0; o >>= 1) s += __shfl_xor_sync(0xffffffff, s, o);
        if (lane == 0) sScore[w][l] = s;
    }
    __syncwarp();

    float sc[LEADS];
    #pragma unroll
    for (int l = 0; l < LEADS; l++) sc[l] = sScore[w][l];
    float m = sc[0];
    #pragma unroll
    for (int l = 1; l < LEADS; l++) m = fmaxf(m, sc[l]);
    float sum = 0.f;
    #pragma unroll
    for (int l = 0; l < LEADS; l++) { sc[l] = expf(sc[l] - m); sum += sc[l]; }
    float inv = 1.f / sum;
    #pragma unroll
    for (int l = 0; l < LEADS; l++) sc[l] *= inv;
    if (lane < LEADS) lw[(size_t)g * LEADS + lane] = sc[lane];

    #pragma unroll
    for (int half = 0; half < 2; half++) {
        int f = lane + 32 * half;
        float mx = -1e30f, sm = 0.f;
        #pragma unroll
        for (int l = 0; l < LEADS; l++) {
            float val = hs[l * 64 + f] * sc[l];
            mx = fmaxf(mx, val);
            sm += val;
        }
        sPool[w][f] = mx;
        sPool[w][64 + f] = sm * (1.f / 12.f);
    }
    __syncwarp();

    float acc = sBl[lane];
    #pragma unroll 16
    for (int f = 0; f < 128; f++) acc += sPool[w][f] * sWl[f * 32 + lane];
    out[(size_t)g * 32 + lane] = fmaxf(acc, 0.f);
}

// ---------------- launch --------------------------------------------------------
extern "C" void kernel_launch(void* const* d_in, const int* in_sizes, int n_in,
                              void* d_out, int out_size) {
    const float* x    = (const float*)d_in[0];
    const int*   ei   = (const int*)d_in[1];
    const int*   srcp = ei;
    const int*   dstp = ei + N_EDGES;
    const float* W1 = (const float*)d_in[3];
    const float* b1 = (const float*)d_in[4];
    const float* W2 = (const float*)d_in[5];
    const float* b2 = (const float*)d_in[6];
    const float* W3 = (const float*)d_in[7];
    const float* b3 = (const float*)d_in[8];
    const float* Wa = (const float*)d_in[9];
    const float* vv = (const float*)d_in[10];
    const float* Wl = (const float*)d_in[11];
    const float* bl = (const float*)d_in[12];

    float* out = (float*)d_out;                                  // [G,32]
    float* lw  = (float*)d_out + (size_t)NUM_GRAPHS * OUT_DIM;   // [G,12]

    __half* hp;  cudaGetSymbolAddress((void**)&hp,  g_hH);
    __half* ap;  cudaGetSymbolAddress((void**)&ap,  g_aggH);

    const int SM1 = (128 + 2 * 64) * (128 + 8) * 2;   // 69632 B
    const int SM2 = (128 + 2 * 64) * (64 + 8) * 2;    // 36864 B
    cudaFuncSetAttribute(k_gemm1,    cudaFuncAttributeMaxDynamicSharedMemorySize, SM1);
    cudaFuncSetAttribute(k_gemm_f16, cudaFuncAttributeMaxDynamicSharedMemorySize, SM2);

    const int T = 256;
    const int gN = (N_NODES + T - 1) / T;
    const int gE = (N_EDGES + T - 1) / T;
    const int GRID = (N_NODES + 127) / 128;
    const int AGG_GRID = (N_QUART * 8 + T - 1) / T;

    // launches 1-3
    k_deg_zero<<<gN, T>>>();
    k_deg_count<<<gE, T>>>(dstp);
    k_dinv<<<gN, T>>>();

    // launch 4 (ncu-profiled slot): layer-1 GEMM
    k_gemm1<<<GRID, 256, SM1>>>(x, W1, hp);

    // CSR build
    k_scan1<<<SCAN_NB, 1024>>>();
    k_scan2<<<1, 1024>>>();
    k_scan3<<<(N_NODES + 1023) / 1024, 1024>>>();
    k_place<<<gE, T>>>(srcp, dstp);

    k_aggregate<<<AGG_GRID, T>>>();
    k_gemm_f16<<<GRID, 256, SM2>>>(ap, W2, b1, hp);
    k_aggregate<<<AGG_GRID, T>>>();
    k_gemm_f16<<<GRID, 256, SM2>>>(ap, W3, b2, hp);
    k_aggregate<<<AGG_GRID, T>>>();

    k_attn<<<(NUM_GRAPHS + 7) / 8, 256>>>(Wa, vv, Wl, bl, b3, out, lw);
}

// round 17
// speedup vs baseline: 1.4769x; 1.0073x over previous
#include <cuda_runtime.h>
#include <cuda_fp16.h>
#include <cuda_bf16.h>

#define N_NODES 600000
#define N_QUART 150000
#define N_EDGES 2400000
#define LEADS 12
#define NUM_GRAPHS 50000
#define F_IN 128
#define HDIM 64
#define OUT_DIM 32

#define SCAN_NB 586   // ceil(600000/1024)

// ---------------- side stream + events (created at static init, reused) --------
static cudaStream_t g_s2 = 0;
static cudaEvent_t  g_evA = 0, g_evB = 0;
static struct GcnInit {
    GcnInit() {
        if (cudaStreamCreateWithFlags(&g_s2, cudaStreamNonBlocking) != cudaSuccess) g_s2 = 0;
        if (cudaEventCreateWithFlags(&g_evA, cudaEventDisableTiming) != cudaSuccess) g_evA = 0;
        if (cudaEventCreateWithFlags(&g_evB, cudaEventDisableTiming) != cudaSuccess) g_evB = 0;
    }
} g_gcn_init;

// ---------------- packed fp32x2 FMA (used in attention) ------------------------
__device__ __forceinline__ void fma2(unsigned long long& d,
                                     unsigned long long a,
                                     unsigned long long b) {
    asm("fma.rn.f32x2 %0, %1, %2, %0;" : "+l"(d) : "l"(a), "l"(b));
}
__device__ __forceinline__ float hsum2(unsigned long long d) {
    float lo = __uint_as_float((unsigned int)(d & 0xffffffffULL));
    float hi = __uint_as_float((unsigned int)(d >> 32));
    return lo + hi;
}

// ---------------- mma m16n8k16, fp32 accumulate ---------------------------------
__device__ __forceinline__ void mma_f16(float* c, const unsigned* a,
                                        unsigned b0, unsigned b1) {
    asm volatile(
        "mma.sync.aligned.m16n8k16.row.col.f32.f16.f16.f32 "
        "{%0,%1,%2,%3}, {%4,%5,%6,%7}, {%8,%9}, {%0,%1,%2,%3};"
        : "+f"(c[0]), "+f"(c[1]), "+f"(c[2]), "+f"(c[3])
        : "r"(a[0]), "r"(a[1]), "r"(a[2]), "r"(a[3]), "r"(b0), "r"(b1));
}

// ---------------- scratch (device globals) ------------------------------------
__device__ __half g_hH  [(size_t)N_NODES * HDIM];  // GEMM output (gather source)
__device__ __half g_aggH[(size_t)N_NODES * HDIM];  // aggregated layer output
__device__ float  g_dinv[N_NODES];
__device__ int    g_deg[N_NODES];
__device__ int    g_rowoff[N_NODES + 1];
__device__ int    g_cursor[N_NODES];
__device__ int    g_csr[N_EDGES];
__device__ int    g_bsum[SCAN_NB];
__device__ int    g_boff[SCAN_NB];

// ---------------- degree / CSR build -------------------------------------------
__global__ void k_deg_zero() {
    int i = blockIdx.x * blockDim.x + threadIdx.x;
    if (i < N_NODES) g_deg[i] = 0;
}

__global__ void k_deg_count(const int* __restrict__ dst) {
    int e = blockIdx.x * blockDim.x + threadIdx.x;
    if (e < N_EDGES) atomicAdd(&g_deg[dst[e]], 1);
}

__global__ void k_dinv() {
    int i = blockIdx.x * blockDim.x + threadIdx.x;
    if (i < N_NODES) g_dinv[i] = rsqrtf((float)(g_deg[i] + 1));
}

__global__ void k_scan1() {
    __shared__ int sh[1024];
    int i = blockIdx.x * 1024 + threadIdx.x;
    int v = (i < N_NODES) ? g_deg[i] : 0;
    sh[threadIdx.x] = v;
    __syncthreads();
    #pragma unroll
    for (int off = 1; off < 1024; off <<= 1) {
        int t = 0;
        if (threadIdx.x >= off) t = sh[threadIdx.x - off];
        __syncthreads();
        if (threadIdx.x >= off) sh[threadIdx.x] += t;
        __syncthreads();
    }
    if (i < N_NODES) g_rowoff[i] = sh[threadIdx.x] - v;   // exclusive
    if (threadIdx.x == 1023) g_bsum[blockIdx.x] = sh[1023];
}

__global__ void k_scan2() {
    __shared__ int sh[1024];
    int v = (threadIdx.x < SCAN_NB) ? g_bsum[threadIdx.x] : 0;
    sh[threadIdx.x] = v;
    __syncthreads();
    #pragma unroll
    for (int off = 1; off < 1024; off <<= 1) {
        int t = 0;
        if (threadIdx.x >= off) t = sh[threadIdx.x - off];
        __syncthreads();
        if (threadIdx.x >= off) sh[threadIdx.x] += t;
        __syncthreads();
    }
    if (threadIdx.x < SCAN_NB) g_boff[threadIdx.x] = sh[threadIdx.x] - v;
}

__global__ void k_scan3() {
    int i = blockIdx.x * blockDim.x + threadIdx.x;
    if (i < N_NODES) {
        int ro = g_rowoff[i] + g_boff[i >> 10];
        g_rowoff[i] = ro;
        g_cursor[i] = ro;
    }
    if (i == 0) g_rowoff[N_NODES] = N_EDGES;
}

__global__ void k_place(const int* __restrict__ src, const int* __restrict__ dst) {
    int e = blockIdx.x * blockDim.x + threadIdx.x;
    if (e < N_EDGES) {
        int pos = atomicAdd(&g_cursor[dst[e]], 1);
        g_csr[pos] = src[e];
    }
}

// ---------------- layer-1 GEMM (fp32 input -> fp16 A, fp16 W hi/lo, 2 HMMA) ----
__global__ void k_gemm1(const float* __restrict__ Ain, const float* __restrict__ W,
                        __half* __restrict__ C) {
    constexpr int K = 128, BM = 128;
    constexpr int KP = K + 8;
    constexpr int KQ = K / 4;
    constexpr int NIT = BM * KQ / 256;   // 16
    extern __shared__ char smem_raw[];
    __half* sA   = (__half*)smem_raw;        // [BM][KP]
    __half* sWhi = sA + BM * KP;             // [64][KP] (transposed)
    __half* sWlo = sWhi + 64 * KP;           // [64][KP]

    const int tid = threadIdx.x;
    const int r0 = blockIdx.x * BM;

    for (int i = tid; i < K * 64; i += 256) {
        int k = i >> 6, c = i & 63;
        float w = W[i];
        __half hi = __float2half_rn(w);
        sWhi[c * KP + k] = hi;
        sWlo[c * KP + k] = __float2half_rn(w - __half2float(hi));
    }

    #pragma unroll
    for (int base = 0; base < NIT; base += 8) {
        float av[8][4];
        #pragma unroll
        for (int j = 0; j < 8; j++) {
            int i = tid + (base + j) * 256;
            int row = i / KQ, kq = i - row * KQ;
            av[j][0] = 0.f; av[j][1] = 0.f; av[j][2] = 0.f; av[j][3] = 0.f;
            if (r0 + row < N_NODES) {
                float4 a = __ldg(((const float4*)Ain) + (size_t)(r0 + row) * KQ + kq);
                av[j][0] = a.x; av[j][1] = a.y; av[j][2] = a.z; av[j][3] = a.w;
            }
        }
        #pragma unroll
        for (int j = 0; j < 8; j++) {
            int i = tid + (base + j) * 256;
            int row = i / KQ, kq = i - row * KQ;
            __half2* pa = (__half2*)(sA + row * KP + kq * 4);
            pa[0] = __floats2half2_rn(av[j][0], av[j][1]);
            pa[1] = __floats2half2_rn(av[j][2], av[j][3]);
        }
    }
    __syncthreads();

    const int warp = tid >> 5;
    const int lane = tid & 31;
    const int g  = lane >> 2;
    const int t2 = (lane & 3) * 2;
    const int wrow = warp * 16;

    float acc[8][4];
    #pragma unroll
    for (int n = 0; n < 8; n++)
        #pragma unroll
        for (int c = 0; c < 4; c++) acc[n][c] = 0.f;

    #pragma unroll
    for (int kb = 0; kb < K / 16; kb++) {
        const int kO = kb * 16 + t2;
        unsigned a[4];
        {
            int rA = wrow + g;
            const unsigned* p0 = (const unsigned*)(sA + rA * KP + kO);
            const unsigned* p8 = (const unsigned*)(sA + (rA + 8) * KP + kO);
            a[0] = p0[0]; a[1] = p8[0]; a[2] = p0[4]; a[3] = p8[4];
        }
        #pragma unroll
        for (int n = 0; n < 8; n++) {
            int rB = n * 8 + g;
            const unsigned* qH = (const unsigned*)(sWhi + rB * KP + kO);
            const unsigned* qL = (const unsigned*)(sWlo + rB * KP + kO);
            unsigned bh0 = qH[0], bh1 = qH[4];
            unsigned bl0 = qL[0], bl1 = qL[4];
            mma_f16(acc[n], a, bh0, bh1);
            mma_f16(acc[n], a, bl0, bl1);
        }
    }

    __half2* C2 = (__half2*)C;
    int r  = r0 + wrow + g;
    int r8 = r + 8;
    float dv  = (r  < N_NODES) ? g_dinv[r]  : 0.f;
    float dv8 = (r8 < N_NODES) ? g_dinv[r8] : 0.f;
    #pragma unroll
    for (int n = 0; n < 8; n++) {
        if (r < N_NODES)
            C2[(size_t)r * 32 + n * 4 + (t2 >> 1)] =
                __floats2half2_rn(acc[n][0] * dv, acc[n][1] * dv);
        if (r8 < N_NODES)
            C2[(size_t)r8 * 32 + n * 4 + (t2 >> 1)] =
                __floats2half2_rn(acc[n][2] * dv8, acc[n][3] * dv8);
    }
}

// ---------------- layers 2/3 GEMM (fp16 input): native fp16 MMA, W hi/lo -------
__global__ void k_gemm_f16(const __half* __restrict__ Ain, const float* __restrict__ W,
                           const float* __restrict__ bias, __half* __restrict__ C) {
    constexpr int K = 64, BM = 128;
    constexpr int KP = K + 8;
    constexpr int KQ = K / 4;
    constexpr int NIT = BM * KQ / 256;   // 8
    extern __shared__ char smem_raw[];
    __half* sA   = (__half*)smem_raw;        // [BM][KP]
    __half* sWhi = sA + BM * KP;             // [64][KP] (transposed)
    __half* sWlo = sWhi + 64 * KP;           // [64][KP]

    const int tid = threadIdx.x;
    const int r0 = blockIdx.x * BM;

    for (int i = tid; i < K * 64; i += 256) {
        int k = i >> 6, c = i & 63;
        float w = W[i];
        __half hi = __float2half_rn(w);
        sWhi[c * KP + k] = hi;
        sWlo[c * KP + k] = __float2half_rn(w - __half2float(hi));
    }

    const float4* B4 = (const float4*)bias;
    {
        float av[NIT][4];
        #pragma unroll
        for (int j = 0; j < NIT; j++) {
            int i = tid + j * 256;
            int row = i / KQ, kq = i - row * KQ;
            av[j][0] = 0.f; av[j][1] = 0.f; av[j][2] = 0.f; av[j][3] = 0.f;
            if (r0 + row < N_NODES) {
                uint2 u = __ldg(((const uint2*)Ain) + (size_t)(r0 + row) * KQ + kq);
                float2 f0 = __half22float2(*(const __half2*)&u.x);
                float2 f1 = __half22float2(*(const __half2*)&u.y);
                av[j][0] = f0.x; av[j][1] = f0.y; av[j][2] = f1.x; av[j][3] = f1.y;
            }
        }
        #pragma unroll
        for (int j = 0; j < NIT; j++) {
            int i = tid + j * 256;
            int row = i / KQ, kq = i - row * KQ;
            float4 b = B4[kq];
            float x0 = fmaxf(av[j][0] + b.x, 0.f);
            float x1 = fmaxf(av[j][1] + b.y, 0.f);
            float x2 = fmaxf(av[j][2] + b.z, 0.f);
            float x3 = fmaxf(av[j][3] + b.w, 0.f);
            __half2* pa = (__half2*)(sA + row * KP + kq * 4);
            pa[0] = __floats2half2_rn(x0, x1);
            pa[1] = __floats2half2_rn(x2, x3);
        }
    }
    __syncthreads();

    const int warp = tid >> 5;
    const int lane = tid & 31;
    const int g  = lane >> 2;
    const int t2 = (lane & 3) * 2;
    const int wrow = warp * 16;

    float acc[8][4];
    #pragma unroll
    for (int n = 0; n < 8; n++)
        #pragma unroll
        for (int c = 0; c < 4; c++) acc[n][c] = 0.f;

    #pragma unroll
    for (int kb = 0; kb < K / 16; kb++) {
        const int kO = kb * 16 + t2;
        unsigned a[4];
        {
            int rA = wrow + g;
            const unsigned* p0 = (const unsigned*)(sA + rA * KP + kO);
            const unsigned* p8 = (const unsigned*)(sA + (rA + 8) * KP + kO);
            a[0] = p0[0]; a[1] = p8[0]; a[2] = p0[4]; a[3] = p8[4];
        }
        #pragma unroll
        for (int n = 0; n < 8; n++) {
            int rB = n * 8 + g;
            const unsigned* qH = (const unsigned*)(sWhi + rB * KP + kO);
            const unsigned* qL = (const unsigned*)(sWlo + rB * KP + kO);
            unsigned bh0 = qH[0], bh1 = qH[4];
            unsigned bl0 = qL[0], bl1 = qL[4];
            mma_f16(acc[n], a, bh0, bh1);
            mma_f16(acc[n], a, bl0, bl1);
        }
    }

    __half2* C2 = (__half2*)C;
    int r  = r0 + wrow + g;
    int r8 = r + 8;
    float dv  = (r  < N_NODES) ? g_dinv[r]  : 0.f;
    float dv8 = (r8 < N_NODES) ? g_dinv[r8] : 0.f;
    #pragma unroll
    for (int n = 0; n < 8; n++) {
        if (r < N_NODES)
            C2[(size_t)r * 32 + n * 4 + (t2 >> 1)] =
                __floats2half2_rn(acc[n][0] * dv, acc[n][1] * dv);
        if (r8 < N_NODES)
            C2[(size_t)r8 * 32 + n * 4 + (t2 >> 1)] =
                __floats2half2_rn(acc[n][2] * dv8, acc[n][3] * dv8);
    }
}

// ---------------- CSR aggregation: 4 nodes/thread + pipelined index loads ------
__device__ __forceinline__ void acc_row(float* a, uint4 r) {
    const __half2* p = (const __half2*)&r;
    #pragma unroll
    for (int i = 0; i < 4; i++) {
        float2 f = __half22float2(p[i]);
        a[2 * i] += f.x; a[2 * i + 1] += f.y;
    }
}

__global__ void k_aggregate() {
    int idx = blockIdx.x * blockDim.x + threadIdx.x;   // over (N/4)*8
    if (idx >= N_QUART * 8) return;
    int n0 = idx >> 3;
    int q = idx & 7;
    const uint4* h4 = (const uint4*)g_hH;

    int node[4], e[4], ee[4];
    float acc[4][8];
    #pragma unroll
    for (int k = 0; k < 4; k++) {
        node[k] = n0 + k * N_QUART;
        #pragma unroll
        for (int i = 0; i < 8; i++) acc[k][i] = 0.f;
    }
    {
        uint4 s0 = h4[(size_t)node[0] * 8 + q];
        uint4 s1 = h4[(size_t)node[1] * 8 + q];
        uint4 s2 = h4[(size_t)node[2] * 8 + q];
        uint4 s3 = h4[(size_t)node[3] * 8 + q];
        acc_row(acc[0], s0);
        acc_row(acc[1], s1);
        acc_row(acc[2], s2);
        acc_row(acc[3], s3);
    }
    #pragma unroll
    for (int k = 0; k < 4; k++) {
        e[k]  = __ldg(&g_rowoff[node[k]]);
        ee[k] = __ldg(&g_rowoff[node[k] + 1]);
    }

    int s[4];
    #pragma unroll
    for (int k = 0; k < 4; k++)
        s[k] = (e[k] < ee[k]) ? __ldg(&g_csr[e[k]]) : -1;

    while ((s[0] >= 0) | (s[1] >= 0) | (s[2] >= 0) | (s[3] >= 0)) {
        uint4 r[4];
        #pragma unroll
        for (int k = 0; k < 4; k++)
            if (s[k] >= 0) r[k] = h4[(size_t)s[k] * 8 + q];
        int sn[4];
        #pragma unroll
        for (int k = 0; k < 4; k++) {
            int en = e[k] + 1;
            sn[k] = (s[k] >= 0 && en < ee[k]) ? __ldg(&g_csr[en]) : -1;
        }
        #pragma unroll
        for (int k = 0; k < 4; k++)
            if (s[k] >= 0) { acc_row(acc[k], r[k]); e[k]++; }
        #pragma unroll
        for (int k = 0; k < 4; k++) s[k] = sn[k];
    }

    #pragma unroll
    for (int k = 0; k < 4; k++) {
        float dv = g_dinv[node[k]];
        uint4 o;
        __half2* po = (__half2*)&o;
        #pragma unroll
        for (int i = 0; i < 4; i++)
            po[i] = __floats2half2_rn(acc[k][2 * i] * dv, acc[k][2 * i + 1] * dv);
        ((uint4*)g_aggH)[(size_t)node[k] * 8 + q] = o;
    }
}

// ---------------- attention + pooling + final linear ---------------------------
__global__ void k_attn(const float* __restrict__ Wa, const float* __restrict__ v,
                       const float* __restrict__ Wl, const float* __restrict__ bl,
                       const float* __restrict__ b3,
                       float* __restrict__ out, float* __restrict__ lw) {
    __shared__ float sWaT[64 * 68];
    __shared__ float sWl[128 * 32];
    __shared__ float sV[64];
    __shared__ float sBl[32];
    __shared__ float sB3[64];
    __shared__ float sH[8][LEADS * 64];
    __shared__ float sScore[8][LEADS];
    __shared__ float sPool[8][128];

    int tid = threadIdx.x;
    for (int i = tid; i < 4096; i += 256) {
        int k = i >> 6, c = i & 63;
        sWaT[c * 68 + k] = Wa[i];
        sWl[i] = Wl[i];
    }
    if (tid < 64) { sV[tid] = v[tid]; sB3[tid] = b3[tid]; }
    if (tid < 32) sBl[tid] = bl[tid];
    __syncthreads();

    int w = tid >> 5, lane = tid & 31;
    int g = blockIdx.x * 8 + w;
    if (g >= NUM_GRAPHS) return;

    float* hs = sH[w];
    const uint4* hg = (const uint4*)(g_aggH + (size_t)g * (LEADS * 64));  // 96 uint4
    #pragma unroll
    for (int j = 0; j < 3; j++) {
        int id = lane + 32 * j;      // 0..95
        uint4 u = hg[id];
        int lead = id >> 3;
        int fb = (id & 7) * 8;
        const __half2* p = (const __half2*)&u;
        #pragma unroll
        for (int i = 0; i < 4; i++) {
            float2 f = __half22float2(p[i]);
            hs[lead * 64 + fb + 2 * i]     = fmaxf(f.x + sB3[fb + 2 * i], 0.f);
            hs[lead * 64 + fb + 2 * i + 1] = fmaxf(f.y + sB3[fb + 2 * i + 1], 0.f);
        }
    }
    __syncwarp();

    unsigned long long e0a[LEADS], e1a[LEADS];
    #pragma unroll
    for (int l = 0; l < LEADS; l++) { e0a[l] = 0ULL; e1a[l] = 0ULL; }
    const float* w0base = sWaT + lane * 68;
    const float* w1base = sWaT + (lane + 32) * 68;
    #pragma unroll 4
    for (int k4 = 0; k4 < 16; k4++) {
        ulonglong2 w0 = *(const ulonglong2*)(w0base + k4 * 4);
        ulonglong2 w1 = *(const ulonglong2*)(w1base + k4 * 4);
        #pragma unroll
        for (int l = 0; l < LEADS; l++) {
            ulonglong2 a = *(const ulonglong2*)(hs + l * 64 + k4 * 4);
            fma2(e0a[l], a.x, w0.x); fma2(e0a[l], a.y, w0.y);
            fma2(e1a[l], a.x, w1.x); fma2(e1a[l], a.y, w1.y);
        }
    }
    float v0 = sV[lane], v1 = sV[lane + 32];
    #pragma unroll
    for (int l = 0; l < LEADS; l++) {
        float s = tanhf(hsum2(e0a[l])) * v0 + tanhf(hsum2(e1a[l])) * v1;
        #pragma unroll
        for (int o = 16; o > 0; o >>= 1) s += __shfl_xor_sync(0xffffffff, s, o);
        if (lane == 0) sScore[w][l] = s;
    }
    __syncwarp();

    float sc[LEADS];
    #pragma unroll
    for (int l = 0; l < LEADS; l++) sc[l] = sScore[w][l];
    float m = sc[0];
    #pragma unroll
    for (int l = 1; l < LEADS; l++) m = fmaxf(m, sc[l]);
    float sum = 0.f;
    #pragma unroll
    for (int l = 0; l < LEADS; l++) { sc[l] = expf(sc[l] - m); sum += sc[l]; }
    float inv = 1.f / sum;
    #pragma unroll
    for (int l = 0; l < LEADS; l++) sc[l] *= inv;
    if (lane < LEADS) lw[(size_t)g * LEADS + lane] = sc[lane];

    #pragma unroll
    for (int half = 0; half < 2; half++) {
        int f = lane + 32 * half;
        float mx = -1e30f, sm = 0.f;
        #pragma unroll
        for (int l = 0; l < LEADS; l++) {
            float val = hs[l * 64 + f] * sc[l];
            mx = fmaxf(mx, val);
            sm += val;
        }
        sPool[w][f] = mx;
        sPool[w][64 + f] = sm * (1.f / 12.f);
    }
    __syncwarp();

    float acc = sBl[lane];
    #pragma unroll 16
    for (int f = 0; f < 128; f++) acc += sPool[w][f] * sWl[f * 32 + lane];
    out[(size_t)g * 32 + lane] = fmaxf(acc, 0.f);
}

// ---------------- launch --------------------------------------------------------
extern "C" void kernel_launch(void* const* d_in, const int* in_sizes, int n_in,
                              void* d_out, int out_size) {
    const float* x    = (const float*)d_in[0];
    const int*   ei   = (const int*)d_in[1];
    const int*   srcp = ei;
    const int*   dstp = ei + N_EDGES;
    const float* W1 = (const float*)d_in[3];
    const float* b1 = (const float*)d_in[4];
    const float* W2 = (const float*)d_in[5];
    const float* b2 = (const float*)d_in[6];
    const float* W3 = (const float*)d_in[7];
    const float* b3 = (const float*)d_in[8];
    const float* Wa = (const float*)d_in[9];
    const float* vv = (const float*)d_in[10];
    const float* Wl = (const float*)d_in[11];
    const float* bl = (const float*)d_in[12];

    float* out = (float*)d_out;                                  // [G,32]
    float* lw  = (float*)d_out + (size_t)NUM_GRAPHS * OUT_DIM;   // [G,12]

    __half* hp;  cudaGetSymbolAddress((void**)&hp,  g_hH);
    __half* ap;  cudaGetSymbolAddress((void**)&ap,  g_aggH);

    const int SM1 = (128 + 2 * 64) * (128 + 8) * 2;   // 69632 B
    const int SM2 = (128 + 2 * 64) * (64 + 8) * 2;    // 36864 B
    cudaFuncSetAttribute(k_gemm1,    cudaFuncAttributeMaxDynamicSharedMemorySize, SM1);
    cudaFuncSetAttribute(k_gemm_f16, cudaFuncAttributeMaxDynamicSharedMemorySize, SM2);

    const int T = 256;
    const int gN = (N_NODES + T - 1) / T;
    const int gE = (N_EDGES + T - 1) / T;
    const int GRID = (N_NODES + 127) / 128;
    const int AGG_GRID = (N_QUART * 8 + T - 1) / T;

    const bool fork = (g_s2 != 0 && g_evA != 0 && g_evB != 0);

    // main stream: degree + dinv (gemm1 epilogue depends on g_dinv!)
    k_deg_zero<<<gN, T>>>();
    k_deg_count<<<gE, T>>>(dstp);
    k_dinv<<<gN, T>>>();

    if (fork) {
        // fork scan/place chain (needs only g_deg) to side stream, overlapping gemm1
        cudaEventRecord(g_evA, 0);
        cudaStreamWaitEvent(g_s2, g_evA, 0);
    }
    cudaStream_t sB = fork ? g_s2 : 0;

    // main stream: layer-1 GEMM (4th submitted kernel -> ncu slot)
    k_gemm1<<<GRID, 256, SM1>>>(x, W1, hp);

    // side stream (or main if no fork): CSR offsets + placement
    k_scan1<<<SCAN_NB, 1024, 0, sB>>>();
    k_scan2<<<1, 1024, 0, sB>>>();
    k_scan3<<<(N_NODES + 1023) / 1024, 1024, 0, sB>>>();
    k_place<<<gE, T, 0, sB>>>(srcp, dstp);

    if (fork) {
        cudaEventRecord(g_evB, g_s2);
        cudaStreamWaitEvent(0, g_evB, 0);
    }

    // main stream: layers + attention
    k_aggregate<<<AGG_GRID, T>>>();
    k_gemm_f16<<<GRID, 256, SM2>>>(ap, W2, b1, hp);
    k_aggregate<<<AGG_GRID, T>>>();
    k_gemm_f16<<<GRID, 256, SM2>>>(ap, W3, b2, hp);
    k_aggregate<<<AGG_GRID, T>>>();

    k_attn<<<(NUM_GRAPHS + 7) / 8, 256>>>(Wa, vv, Wl, bl, b3, out, lw);
}